// round 7
// baseline (speedup 1.0000x reference)
#include <cuda_runtime.h>
#include <cuda_bf16.h>
#include <math.h>
#include <stdint.h>

// Problem constants
constexpr int Bc  = 4;
constexpr int Sq  = 2048;
constexpr int Dm  = 1024;
constexpr int Hh  = 16;
constexpr int HDd = 64;
constexpr int Mtot = Bc * Sq;           // 8192

// Scratch (device globals: allocation-free per harness rules)
__device__ __nv_bfloat16 g_xh[(size_t)Mtot * Dm];
__device__ __nv_bfloat16 g_xl[(size_t)Mtot * Dm];
__device__ __nv_bfloat16 g_wh[(size_t)4 * Dm * Dm];
__device__ __nv_bfloat16 g_wl[(size_t)4 * Dm * Dm];
__device__ __nv_bfloat16 g_qh[(size_t)Mtot * Dm];
__device__ __nv_bfloat16 g_ql[(size_t)Mtot * Dm];
__device__ __nv_bfloat16 g_kh[(size_t)Mtot * Dm];
__device__ __nv_bfloat16 g_kl[(size_t)Mtot * Dm];
__device__ __nv_bfloat16 g_vh[(size_t)Mtot * Dm];
__device__ __nv_bfloat16 g_vl[(size_t)Mtot * Dm];
__device__ __nv_bfloat16 g_ch[(size_t)Mtot * Dm];
__device__ __nv_bfloat16 g_cl[(size_t)Mtot * Dm];

// ---------------------------------------------------------------------------
// PTX helpers (sm_80-compatible subset: ldmatrix / mma.sync / cp.async)
// ---------------------------------------------------------------------------
__device__ __forceinline__ uint32_t smem_u32(const void* p) {
    uint32_t a;
    asm("{ .reg .u64 t; cvta.to.shared.u64 t, %1; cvt.u32.u64 %0, t; }" : "=r"(a) : "l"(p));
    return a;
}
__device__ __forceinline__ void ldm_x4(uint32_t (&r)[4], uint32_t saddr) {
    asm volatile("ldmatrix.sync.aligned.m8n8.x4.shared.b16 {%0,%1,%2,%3}, [%4];"
        : "=r"(r[0]), "=r"(r[1]), "=r"(r[2]), "=r"(r[3]) : "r"(saddr));
}
__device__ __forceinline__ void ldm_x4_t(uint32_t (&r)[4], uint32_t saddr) {
    asm volatile("ldmatrix.sync.aligned.m8n8.x4.trans.shared.b16 {%0,%1,%2,%3}, [%4];"
        : "=r"(r[0]), "=r"(r[1]), "=r"(r[2]), "=r"(r[3]) : "r"(saddr));
}
__device__ __forceinline__ void mma16816(float (&c)[4], const uint32_t (&a)[4],
                                         uint32_t b0, uint32_t b1) {
    asm volatile("mma.sync.aligned.m16n8k16.row.col.f32.bf16.bf16.f32 "
        "{%0,%1,%2,%3}, {%4,%5,%6,%7}, {%8,%9}, {%0,%1,%2,%3};"
        : "+f"(c[0]), "+f"(c[1]), "+f"(c[2]), "+f"(c[3])
        : "r"(a[0]), "r"(a[1]), "r"(a[2]), "r"(a[3]), "r"(b0), "r"(b1));
}
__device__ __forceinline__ void cp16(uint32_t dst, const void* src) {
    asm volatile("cp.async.cg.shared.global [%0], [%1], 16;" :: "r"(dst), "l"(src) : "memory");
}
#define CP_COMMIT() asm volatile("cp.async.commit_group;" ::: "memory")
#define CP_WAIT(n)  asm volatile("cp.async.wait_group %0;" :: "n"(n) : "memory")

__device__ __forceinline__ uint32_t bf2(float a, float b) {
    __nv_bfloat162 t = __floats2bfloat162_rn(a, b);
    return *reinterpret_cast<uint32_t*>(&t);
}
__device__ __forceinline__ float bf16rt(float a) {
    return __bfloat162float(__float2bfloat16(a));
}
__device__ __forceinline__ uint32_t swz(int row, int chunk) {
    return (uint32_t)(row * 128 + ((chunk ^ (row & 7)) * 16));
}

// ---------------------------------------------------------------------------
// fp32 -> bf16 hi/lo split conversion (x: 1D grid; weights: y-indexed 4x)
// ---------------------------------------------------------------------------
__global__ __launch_bounds__(256) void cvt_split_kernel(const float* __restrict__ in,
                                                        __nv_bfloat16* __restrict__ hi,
                                                        __nv_bfloat16* __restrict__ lo,
                                                        int n4)
{
    const int i = blockIdx.x * blockDim.x + threadIdx.x;
    if (i >= n4) return;
    const float4 v = ((const float4*)in)[i];
    union { __nv_bfloat16 b[4]; uint2 u; } H, L;
    const float vv[4] = {v.x, v.y, v.z, v.w};
#pragma unroll
    for (int j = 0; j < 4; j++) {
        H.b[j] = __float2bfloat16(vv[j]);
        L.b[j] = __float2bfloat16(vv[j] - __bfloat162float(H.b[j]));
    }
    ((uint2*)hi)[i] = H.u;
    ((uint2*)lo)[i] = L.u;
}

__global__ __launch_bounds__(256) void cvt_split_w_kernel(
    const float* __restrict__ w0, const float* __restrict__ w1,
    const float* __restrict__ w2, const float* __restrict__ w3,
    __nv_bfloat16* __restrict__ hi, __nv_bfloat16* __restrict__ lo)
{
    const int n4 = Dm * Dm / 4;
    const int i = blockIdx.x * blockDim.x + threadIdx.x;
    if (i >= n4) return;
    const int wsel = blockIdx.y;
    const float* in = wsel == 0 ? w0 : wsel == 1 ? w1 : wsel == 2 ? w2 : w3;
    const size_t off = (size_t)wsel * n4 + i;
    const float4 v = ((const float4*)in)[i];
    union { __nv_bfloat16 b[4]; uint2 u; } H, L;
    const float vv[4] = {v.x, v.y, v.z, v.w};
#pragma unroll
    for (int j = 0; j < 4; j++) {
        H.b[j] = __float2bfloat16(vv[j]);
        L.b[j] = __float2bfloat16(vv[j] - __bfloat162float(H.b[j]));
    }
    ((uint2*)hi)[off] = H.u;
    ((uint2*)lo)[off] = L.u;
}

// ---------------------------------------------------------------------------
// HMMA bf16x3 GEMM: 128x128 CTA tile, BK=32, 8 warps (2x4), cp.async 3-stage.
// blockIdx.z selects among up to 3 (W, bias, out) sets (fused Q/K/V).
// ---------------------------------------------------------------------------
constexpr int BKg = 32;
constexpr int NKC = Dm / BKg;
constexpr int TILE_BYTES = 128 * 128;
constexpr int STAGE_BYTES = 2 * TILE_BYTES;     // 32 KB (A + B tiles)
constexpr int GEMM_SMEM = 3 * STAGE_BYTES;      // 96 KB, 3-stage ring

template <bool SPLIT>
__global__ __launch_bounds__(256) void hmma_gemm_kernel(
    const __nv_bfloat16* __restrict__ Ah, const __nv_bfloat16* __restrict__ Al,
    const __nv_bfloat16* __restrict__ Bh0, const __nv_bfloat16* __restrict__ Bh1,
    const __nv_bfloat16* __restrict__ Bh2,
    const __nv_bfloat16* __restrict__ Bl0, const __nv_bfloat16* __restrict__ Bl1,
    const __nv_bfloat16* __restrict__ Bl2,
    const float* __restrict__ bias0, const float* __restrict__ bias1,
    const float* __restrict__ bias2,
    float* __restrict__ outF,
    __nv_bfloat16* __restrict__ oh0, __nv_bfloat16* __restrict__ oh1,
    __nv_bfloat16* __restrict__ oh2,
    __nv_bfloat16* __restrict__ ol0, __nv_bfloat16* __restrict__ ol1,
    __nv_bfloat16* __restrict__ ol2)
{
    extern __shared__ char sm[];
    const uint32_t smb = smem_u32(sm);
    const int z    = blockIdx.z;
    const __nv_bfloat16* Bh = z == 0 ? Bh0 : z == 1 ? Bh1 : Bh2;
    const __nv_bfloat16* Bl = z == 0 ? Bl0 : z == 1 ? Bl1 : Bl2;
    const float* bias       = z == 0 ? bias0 : z == 1 ? bias1 : bias2;
    __nv_bfloat16* outH     = z == 0 ? oh0 : z == 1 ? oh1 : oh2;
    __nv_bfloat16* outL     = z == 0 ? ol0 : z == 1 ? ol1 : ol2;
    const float scale = (SPLIT && z == 0) ? 0.125f : 1.0f;

    const int t    = threadIdx.x;
    const int wid  = t >> 5;
    const int lane = t & 31;
    const int m0   = blockIdx.y * 128;
    const int n0   = blockIdx.x * 128;
    const int wm   = (wid & 1) * 64;
    const int wn   = (wid >> 1) * 32;

    auto load_stage = [&](int s, int kc) {
        const uint32_t ab = smb + s * STAGE_BYTES;
        const uint32_t bb = ab + TILE_BYTES;
#pragma unroll
        for (int i = 0; i < 4; i++) {
            const int idx  = t + i * 256;
            const int row  = idx >> 3;
            const int c    = idx & 7;
            const int kofs = kc * BKg + (c & 3) * 8;
            const __nv_bfloat16* sa = (c < 4 ? Ah : Al) + (size_t)(m0 + row) * Dm + kofs;
            cp16(ab + swz(row, c), sa);
            const __nv_bfloat16* sb = (c < 4 ? Bh : Bl) + (size_t)(n0 + row) * Dm + kofs;
            cp16(bb + swz(row, c), sb);
        }
        CP_COMMIT();
    };

    float acc[4][4][4];
#pragma unroll
    for (int i = 0; i < 4; i++)
#pragma unroll
        for (int j = 0; j < 4; j++)
#pragma unroll
            for (int r = 0; r < 4; r++) acc[i][j][r] = 0.0f;

    load_stage(0, 0);
    load_stage(1, 1);

    const int lrow = lane & 15;
    const int lsel = lane >> 4;

    int s = 0;
    for (int kc = 0; kc < NKC; kc++) {
        if (kc + 1 < NKC) { CP_WAIT(1); } else { CP_WAIT(0); }
        __syncthreads();
        if (kc + 2 < NKC) {
            int s2 = s + 2; if (s2 >= 3) s2 -= 3;
            load_stage(s2, kc + 2);
        }

        const uint32_t ab = smb + s * STAGE_BYTES;
        const uint32_t bb = ab + TILE_BYTES;

#pragma unroll
        for (int k16 = 0; k16 < 2; k16++) {
            const int ch = k16 * 2 + lsel;
            uint32_t a_h[4][4], a_l[4][4];
#pragma unroll
            for (int mt = 0; mt < 4; mt++) {
                const int row = wm + mt * 16 + lrow;
                ldm_x4(a_h[mt], ab + swz(row, ch));
                ldm_x4(a_l[mt], ab + swz(row, ch + 4));
            }
            uint32_t b_h[2][4], b_l[2][4];
#pragma unroll
            for (int nt = 0; nt < 2; nt++) {
                const int row = wn + nt * 16 + lrow;
                ldm_x4(b_h[nt], bb + swz(row, ch));
                ldm_x4(b_l[nt], bb + swz(row, ch + 4));
            }
#pragma unroll
            for (int mt = 0; mt < 4; mt++) {
#pragma unroll
                for (int n8 = 0; n8 < 4; n8++) {
                    const int nt = n8 >> 1, sl = n8 & 1;
                    mma16816(acc[mt][n8], a_h[mt], b_h[nt][sl], b_h[nt][sl + 2]);
                    mma16816(acc[mt][n8], a_h[mt], b_l[nt][sl], b_l[nt][sl + 2]);
                    mma16816(acc[mt][n8], a_l[mt], b_h[nt][sl], b_h[nt][sl + 2]);
                }
            }
        }
        if (++s == 3) s = 0;
    }

#pragma unroll
    for (int mt = 0; mt < 4; mt++) {
#pragma unroll
        for (int n8 = 0; n8 < 4; n8++) {
            const int r0 = m0 + wm + mt * 16 + (lane >> 2);
            const int c0 = n0 + wn + n8 * 8 + (lane & 3) * 2;
#pragma unroll
            for (int half = 0; half < 2; half++) {
                const int m = r0 + half * 8;
                const int b_ = m / Sq;
                const int s_ = m % Sq;
                const float v0 = (acc[mt][n8][half * 2 + 0] + bias[c0]) * scale;
                const float v1 = (acc[mt][n8][half * 2 + 1] + bias[c0 + 1]) * scale;
                if (SPLIT) {
                    const int h_ = c0 >> 6;
                    const int d_ = c0 & 63;
                    const size_t off =
                        ((((size_t)(b_ * Hh + h_)) * Sq + s_) * HDd + d_) >> 1;
                    ((uint32_t*)outH)[off] = bf2(v0, v1);
                    ((uint32_t*)outL)[off] = bf2(v0 - bf16rt(v0), v1 - bf16rt(v1));
                } else {
                    float* dst = outF + (size_t)m * Dm + c0;
                    dst[0] = v0; dst[1] = v1;
                }
            }
        }
    }
}

// ---------------------------------------------------------------------------
// HMMA flash attention: CTA = (128 queries, head, batch), 8 warps x 16 rows,
// 256 threads, 2 CTAs/SM. K and V double-buffered via cp.async. Longest CTAs
// (largest qt) launch first: qt = gridDim.x - 1 - blockIdx.x.
// SMEM: Q 32KB | KV 2-stage x 32KB | mask 2x256B = 96.5KB
// ---------------------------------------------------------------------------
constexpr int FA_QSZ   = 32768;                   // Qh 16K + Ql 16K
constexpr int FA_STAGE = 32768;                   // Kh,Kl,Vh,Vl 8K each
constexpr int FA_MOFF  = FA_QSZ + 2 * FA_STAGE;   // 98304
constexpr int FA_SMEM  = FA_MOFF + 512;           // 98816

__global__ __launch_bounds__(256, 2) void fa_hmma_kernel(
    const __nv_bfloat16* __restrict__ Qh, const __nv_bfloat16* __restrict__ Ql,
    const __nv_bfloat16* __restrict__ Kh, const __nv_bfloat16* __restrict__ Kl,
    const __nv_bfloat16* __restrict__ Vh, const __nv_bfloat16* __restrict__ Vl,
    const int* __restrict__ maskg,
    __nv_bfloat16* __restrict__ Ch, __nv_bfloat16* __restrict__ Cl)
{
    extern __shared__ char sm[];
    const uint32_t smb = smem_u32(sm);
    const int t    = threadIdx.x;
    const int w    = t >> 5;
    const int lane = t & 31;
    const int qt   = gridDim.x - 1 - blockIdx.x;   // longest-first
    const int h    = blockIdx.y;
    const int b    = blockIdx.z;
    const size_t hb = ((size_t)(b * Hh + h)) * Sq * HDd;

    const uint32_t qhb = smb;
    const uint32_t qlb = smb + 16384;
    const int nkt = 2 * qt + 2;                    // 64-wide K tiles

    // Prologue: Q tile (128 rows, hi+lo)
    {
        const char* srcH = (const char*)(Qh + hb + (size_t)qt * 128 * HDd);
        const char* srcL = (const char*)(Ql + hb + (size_t)qt * 128 * HDd);
#pragma unroll
        for (int i = 0; i < 4; i++) {
            const int idx = t + i * 256;           // 0..1023
            const int row = idx >> 3, c = idx & 7;
            cp16(qhb + swz(row, c), srcH + idx * 16);
            cp16(qlb + swz(row, c), srcL + idx * 16);
        }
    }
    auto load_kv = [&](int s, int kt2) {
        const uint32_t kb = smb + FA_QSZ + s * FA_STAGE;
        const char* sKH = (const char*)(Kh + hb + (size_t)kt2 * 64 * HDd);
        const char* sKL = (const char*)(Kl + hb + (size_t)kt2 * 64 * HDd);
        const char* sVH = (const char*)(Vh + hb + (size_t)kt2 * 64 * HDd);
        const char* sVL = (const char*)(Vl + hb + (size_t)kt2 * 64 * HDd);
#pragma unroll
        for (int i = 0; i < 2; i++) {
            const int idx = t + i * 256;           // 0..511
            const int row = idx >> 3, c = idx & 7;
            cp16(kb + swz(row, c), sKH + idx * 16);
            cp16(kb + 8192  + swz(row, c), sKL + idx * 16);
            cp16(kb + 16384 + swz(row, c), sVH + idx * 16);
            cp16(kb + 24576 + swz(row, c), sVL + idx * 16);
        }
        if (t < 16) cp16(smb + FA_MOFF + s * 256 + t * 16,
                         maskg + b * Sq + kt2 * 64 + t * 4);
        CP_COMMIT();
    };
    load_kv(0, 0);

    const int lrow  = lane & 15;
    const int lsel  = lane >> 4;
    const int rl    = lane >> 2;
    const int cbase = (lane & 3) * 2;
    const int wr0   = w * 16;

    float m_i[2] = {-INFINITY, -INFINITY};
    float l_i[2] = {0.0f, 0.0f};
    float o[8][4];
#pragma unroll
    for (int n8 = 0; n8 < 8; n8++)
#pragma unroll
        for (int c = 0; c < 4; c++) o[n8][c] = 0.0f;

    for (int kt2 = 0; kt2 < nkt; kt2++) {
        const int s = kt2 & 1;

        __syncthreads();                 // all warps done with stage s^1
        if (kt2 + 1 < nkt) { load_kv(s ^ 1, kt2 + 1); CP_WAIT(1); }
        else               { CP_WAIT(0); }
        __syncthreads();                 // stage s visible to all warps

        const uint32_t kb  = smb + FA_QSZ + s * FA_STAGE;
        const uint32_t khb = kb, klb = kb + 8192;
        const uint32_t vhb = kb + 16384, vlb = kb + 24576;
        const int* msk = (const int*)(sm + FA_MOFF + s * 256);

        // ---- S = Q @ K^T (bf16x3) ----
        float sc[8][4];
#pragma unroll
        for (int n8 = 0; n8 < 8; n8++)
#pragma unroll
            for (int c = 0; c < 4; c++) sc[n8][c] = 0.0f;

#pragma unroll
        for (int k16 = 0; k16 < 4; k16++) {
            const int ch = k16 * 2 + lsel;
            uint32_t qf_h[4], qf_l[4];
            ldm_x4(qf_h, qhb + swz(wr0 + lrow, ch));
            ldm_x4(qf_l, qlb + swz(wr0 + lrow, ch));
            uint32_t kf_h[4][4], kf_l[4][4];
#pragma unroll
            for (int nt = 0; nt < 4; nt++) {
                ldm_x4(kf_h[nt], khb + swz(nt * 16 + lrow, ch));
                ldm_x4(kf_l[nt], klb + swz(nt * 16 + lrow, ch));
            }
#pragma unroll
            for (int n8 = 0; n8 < 8; n8++) {
                const int nt = n8 >> 1, sl = n8 & 1;
                mma16816(sc[n8], qf_h, kf_h[nt][sl], kf_h[nt][sl + 2]);
                mma16816(sc[n8], qf_h, kf_l[nt][sl], kf_l[nt][sl + 2]);
                mma16816(sc[n8], qf_l, kf_h[nt][sl], kf_h[nt][sl + 2]);
            }
        }

        // ---- masking (pad overrides causal, reference order) ----
        const bool diag = (kt2 >= 2 * qt);     // last two K tiles touch diagonal
        const int qi0 = qt * 128 + wr0 + rl;
#pragma unroll
        for (int n8 = 0; n8 < 8; n8++) {
#pragma unroll
            for (int c = 0; c < 4; c++) {
                const int colL = n8 * 8 + cbase + (c & 1);
                const int mv = msk[colL];
                if (mv == 0) sc[n8][c] = -1e9f;
                else if (diag) {
                    const int kj = kt2 * 64 + colL;
                    const int qi = qi0 + (c >> 1) * 8;
                    if (kj > qi) sc[n8][c] = -INFINITY;
                }
            }
        }

        // ---- online softmax (rows rl, rl+8) ----
#pragma unroll
        for (int r = 0; r < 2; r++) {
            float mx = -INFINITY;
#pragma unroll
            for (int n8 = 0; n8 < 8; n8++)
                mx = fmaxf(mx, fmaxf(sc[n8][2 * r], sc[n8][2 * r + 1]));
            mx = fmaxf(mx, __shfl_xor_sync(0xffffffffu, mx, 1));
            mx = fmaxf(mx, __shfl_xor_sync(0xffffffffu, mx, 2));
            const float mnew  = fmaxf(m_i[r], mx);
            const float alpha = __expf(m_i[r] - mnew);
            float sum = 0.0f;
#pragma unroll
            for (int n8 = 0; n8 < 8; n8++) {
                const float p0 = __expf(sc[n8][2 * r]     - mnew);
                const float p1 = __expf(sc[n8][2 * r + 1] - mnew);
                sc[n8][2 * r] = p0; sc[n8][2 * r + 1] = p1;
                sum += p0 + p1;
            }
            sum += __shfl_xor_sync(0xffffffffu, sum, 1);
            sum += __shfl_xor_sync(0xffffffffu, sum, 2);
            l_i[r] = l_i[r] * alpha + sum;
            m_i[r] = mnew;
#pragma unroll
            for (int n8 = 0; n8 < 8; n8++) {
                o[n8][2 * r] *= alpha; o[n8][2 * r + 1] *= alpha;
            }
        }

        // ---- P -> bf16 hi/lo A-fragments ----
        uint32_t pah[4][4], pal[4][4];
#pragma unroll
        for (int j = 0; j < 4; j++) {
#pragma unroll
            for (int u = 0; u < 4; u++) {
                const int tile = 2 * j + (u >> 1);
                const int ci   = (u & 1) * 2;
                const float p0 = sc[tile][ci], p1 = sc[tile][ci + 1];
                pah[j][u] = bf2(p0, p1);
                pal[j][u] = bf2(p0 - bf16rt(p0), p1 - bf16rt(p1));
            }
        }

        // ---- O += P @ V (bf16x3), V via ldmatrix.trans ----
#pragma unroll
        for (int j = 0; j < 4; j++) {
            const int mrow = 16 * j + ((lane >> 3) & 1) * 8 + (lane & 7);
            uint32_t vf_h[4][4], vf_l[4][4];
#pragma unroll
            for (int hp = 0; hp < 4; hp++) {
                const int chv = hp * 2 + (lane >> 4);
                ldm_x4_t(vf_h[hp], vhb + swz(mrow, chv));
                ldm_x4_t(vf_l[hp], vlb + swz(mrow, chv));
            }
#pragma unroll
            for (int n8 = 0; n8 < 8; n8++) {
                const int hp = n8 >> 1, q_ = n8 & 1;
                mma16816(o[n8], pah[j], vf_h[hp][2 * q_], vf_h[hp][2 * q_ + 1]);
                mma16816(o[n8], pal[j], vf_h[hp][2 * q_], vf_h[hp][2 * q_ + 1]);
                mma16816(o[n8], pah[j], vf_l[hp][2 * q_], vf_l[hp][2 * q_ + 1]);
            }
        }
    }

    // ---- normalize + write ctx hi/lo [B,S,D] ----
#pragma unroll
    for (int r = 0; r < 2; r++) {
        const float inv = 1.0f / l_i[r];
        const int m = qt * 128 + wr0 + rl + r * 8;
        const size_t rowoff = ((size_t)b * Sq + m) * Dm + h * HDd;
#pragma unroll
        for (int n8 = 0; n8 < 8; n8++) {
            const int col = n8 * 8 + cbase;
            const float v0 = o[n8][2 * r] * inv;
            const float v1 = o[n8][2 * r + 1] * inv;
            ((uint32_t*)(Ch + rowoff + col))[0] = bf2(v0, v1);
            ((uint32_t*)(Cl + rowoff + col))[0] =
                bf2(v0 - bf16rt(v0), v1 - bf16rt(v1));
        }
    }
}

// ---------------------------------------------------------------------------
// Launch
// ---------------------------------------------------------------------------
extern "C" void kernel_launch(void* const* d_in, const int* in_sizes, int n_in,
                              void* d_out, int out_size)
{
    const float* x  = nullptr;
    const int*   am = nullptr;
    const float* Ws[4] = {nullptr, nullptr, nullptr, nullptr};
    const float* bs[4] = {nullptr, nullptr, nullptr, nullptr};
    int wi = 0, bi = 0;
    for (int i = 0; i < n_in; i++) {
        const long sz = in_sizes[i];
        if (sz == (long)Mtot * Dm)      x = (const float*)d_in[i];
        else if (sz == (long)Mtot)      am = (const int*)d_in[i];
        else if (sz == (long)Dm * Dm) { if (wi < 4) Ws[wi++] = (const float*)d_in[i]; }
        else if (sz == (long)Dm)      { if (bi < 4) bs[bi++] = (const float*)d_in[i]; }
    }

    __nv_bfloat16 *xh, *xl, *wh, *wl, *qh, *ql, *kh, *kl, *vh, *vl, *ch, *cl;
    cudaGetSymbolAddress((void**)&xh, g_xh);
    cudaGetSymbolAddress((void**)&xl, g_xl);
    cudaGetSymbolAddress((void**)&wh, g_wh);
    cudaGetSymbolAddress((void**)&wl, g_wl);
    cudaGetSymbolAddress((void**)&qh, g_qh);
    cudaGetSymbolAddress((void**)&ql, g_ql);
    cudaGetSymbolAddress((void**)&kh, g_kh);
    cudaGetSymbolAddress((void**)&kl, g_kl);
    cudaGetSymbolAddress((void**)&vh, g_vh);
    cudaGetSymbolAddress((void**)&vl, g_vl);
    cudaGetSymbolAddress((void**)&ch, g_ch);
    cudaGetSymbolAddress((void**)&cl, g_cl);

    cudaFuncSetAttribute(hmma_gemm_kernel<true>,
                         cudaFuncAttributeMaxDynamicSharedMemorySize, GEMM_SMEM);
    cudaFuncSetAttribute(hmma_gemm_kernel<false>,
                         cudaFuncAttributeMaxDynamicSharedMemorySize, GEMM_SMEM);
    cudaFuncSetAttribute(fa_hmma_kernel,
                         cudaFuncAttributeMaxDynamicSharedMemorySize, FA_SMEM);

    // Split inputs into bf16 hi/lo
    const int n4x = Mtot * Dm / 4;
    const int n4w = Dm * Dm / 4;
    cvt_split_kernel<<<(n4x + 255) / 256, 256>>>(x, xh, xl, n4x);
    cvt_split_w_kernel<<<dim3((n4w + 255) / 256, 4), 256>>>(
        Ws[0], Ws[1], Ws[2], Ws[3], wh, wl);

    const size_t WSZ = (size_t)Dm * Dm;

    // Fused Q/K/V projections (z selects W), Q carries softmax scale
    const dim3 gqkv(Dm / 128, Mtot / 128, 3);
    hmma_gemm_kernel<true><<<gqkv, 256, GEMM_SMEM>>>(
        xh, xl,
        wh + 0 * WSZ, wh + 1 * WSZ, wh + 2 * WSZ,
        wl + 0 * WSZ, wl + 1 * WSZ, wl + 2 * WSZ,
        bs[0], bs[1], bs[2],
        nullptr,
        qh, kh, vh,
        ql, kl, vl);

    // Attention (HMMA, 128-query tiles, 2 CTAs/SM, longest-first)
    const dim3 ga(Sq / 128, Hh, Bc);
    fa_hmma_kernel<<<ga, 256, FA_SMEM>>>(qh, ql, kh, kl, vh, vl, am, ch, cl);

    // Output projection
    const dim3 gg(Dm / 128, Mtot / 128, 1);
    hmma_gemm_kernel<false><<<gg, 256, GEMM_SMEM>>>(
        ch, cl,
        wh + 3 * WSZ, wh + 3 * WSZ, wh + 3 * WSZ,
        wl + 3 * WSZ, wl + 3 * WSZ, wl + 3 * WSZ,
        bs[3], bs[3], bs[3],
        (float*)d_out,
        nullptr, nullptr, nullptr,
        nullptr, nullptr, nullptr);
}

// round 8
// speedup vs baseline: 1.3389x; 1.3389x over previous
#include <cuda_runtime.h>
#include <cuda_bf16.h>
#include <cuda_fp16.h>
#include <math.h>
#include <stdint.h>

// Problem constants
constexpr int Bc  = 4;
constexpr int Sq  = 2048;
constexpr int Dm  = 1024;
constexpr int Hh  = 16;
constexpr int HDd = 64;
constexpr int Mtot = Bc * Sq;           // 8192

// Scratch (device globals: allocation-free per harness rules)
__device__ __half g_xf[(size_t)Mtot * Dm];            // x in fp16
__device__ __half g_wh[(size_t)4 * Dm * Dm];          // W hi fp16
__device__ __half g_wl[(size_t)4 * Dm * Dm];          // W lo fp16
__device__ __half g_cf[(size_t)Mtot * Dm];            // ctx in fp16
__device__ __nv_bfloat16 g_qh[(size_t)Mtot * Dm];
__device__ __nv_bfloat16 g_ql[(size_t)Mtot * Dm];
__device__ __nv_bfloat16 g_kh[(size_t)Mtot * Dm];
__device__ __nv_bfloat16 g_kl[(size_t)Mtot * Dm];
__device__ __nv_bfloat16 g_vh[(size_t)Mtot * Dm];
__device__ __nv_bfloat16 g_vl[(size_t)Mtot * Dm];

// ---------------------------------------------------------------------------
// PTX helpers
// ---------------------------------------------------------------------------
__device__ __forceinline__ uint32_t smem_u32(const void* p) {
    uint32_t a;
    asm("{ .reg .u64 t; cvta.to.shared.u64 t, %1; cvt.u32.u64 %0, t; }" : "=r"(a) : "l"(p));
    return a;
}
__device__ __forceinline__ void ldm_x4(uint32_t (&r)[4], uint32_t saddr) {
    asm volatile("ldmatrix.sync.aligned.m8n8.x4.shared.b16 {%0,%1,%2,%3}, [%4];"
        : "=r"(r[0]), "=r"(r[1]), "=r"(r[2]), "=r"(r[3]) : "r"(saddr));
}
__device__ __forceinline__ void ldm_x4_t(uint32_t (&r)[4], uint32_t saddr) {
    asm volatile("ldmatrix.sync.aligned.m8n8.x4.trans.shared.b16 {%0,%1,%2,%3}, [%4];"
        : "=r"(r[0]), "=r"(r[1]), "=r"(r[2]), "=r"(r[3]) : "r"(saddr));
}
__device__ __forceinline__ void mma_bf16(float (&c)[4], const uint32_t (&a)[4],
                                         uint32_t b0, uint32_t b1) {
    asm volatile("mma.sync.aligned.m16n8k16.row.col.f32.bf16.bf16.f32 "
        "{%0,%1,%2,%3}, {%4,%5,%6,%7}, {%8,%9}, {%0,%1,%2,%3};"
        : "+f"(c[0]), "+f"(c[1]), "+f"(c[2]), "+f"(c[3])
        : "r"(a[0]), "r"(a[1]), "r"(a[2]), "r"(a[3]), "r"(b0), "r"(b1));
}
__device__ __forceinline__ void mma_fp16(float (&c)[4], const uint32_t (&a)[4],
                                         uint32_t b0, uint32_t b1) {
    asm volatile("mma.sync.aligned.m16n8k16.row.col.f32.f16.f16.f32 "
        "{%0,%1,%2,%3}, {%4,%5,%6,%7}, {%8,%9}, {%0,%1,%2,%3};"
        : "+f"(c[0]), "+f"(c[1]), "+f"(c[2]), "+f"(c[3])
        : "r"(a[0]), "r"(a[1]), "r"(a[2]), "r"(a[3]), "r"(b0), "r"(b1));
}
__device__ __forceinline__ void cp16(uint32_t dst, const void* src) {
    asm volatile("cp.async.cg.shared.global [%0], [%1], 16;" :: "r"(dst), "l"(src) : "memory");
}
#define CP_COMMIT() asm volatile("cp.async.commit_group;" ::: "memory")
#define CP_WAIT(n)  asm volatile("cp.async.wait_group %0;" :: "n"(n) : "memory")

__device__ __forceinline__ uint32_t bf2(float a, float b) {
    __nv_bfloat162 t = __floats2bfloat162_rn(a, b);
    return *reinterpret_cast<uint32_t*>(&t);
}
__device__ __forceinline__ float bf16rt(float a) {
    return __bfloat162float(__float2bfloat16(a));
}
__device__ __forceinline__ uint32_t swz(int row, int chunk) {
    return (uint32_t)(row * 128 + ((chunk ^ (row & 7)) * 16));
}

// ---------------------------------------------------------------------------
// Conversions: x -> fp16; weights -> fp16 hi/lo (y-indexed over 4 weights)
// ---------------------------------------------------------------------------
__global__ __launch_bounds__(256) void cvt_x_kernel(const float* __restrict__ in,
                                                    __half* __restrict__ out, int n4)
{
    const int i = blockIdx.x * blockDim.x + threadIdx.x;
    if (i >= n4) return;
    const float4 v = ((const float4*)in)[i];
    uint2 u;
    __half2 h01 = __floats2half2_rn(v.x, v.y);
    __half2 h23 = __floats2half2_rn(v.z, v.w);
    u.x = *reinterpret_cast<uint32_t*>(&h01);
    u.y = *reinterpret_cast<uint32_t*>(&h23);
    ((uint2*)out)[i] = u;
}

__global__ __launch_bounds__(256) void cvt_w_kernel(
    const float* __restrict__ w0, const float* __restrict__ w1,
    const float* __restrict__ w2, const float* __restrict__ w3,
    __half* __restrict__ hi, __half* __restrict__ lo)
{
    const int n4 = Dm * Dm / 4;
    const int i = blockIdx.x * blockDim.x + threadIdx.x;
    if (i >= n4) return;
    const int wsel = blockIdx.y;
    const float* in = wsel == 0 ? w0 : wsel == 1 ? w1 : wsel == 2 ? w2 : w3;
    const size_t off = (size_t)wsel * n4 + i;
    const float4 v = ((const float4*)in)[i];
    union { __half h[4]; uint2 u; } H, L;
    const float vv[4] = {v.x, v.y, v.z, v.w};
#pragma unroll
    for (int j = 0; j < 4; j++) {
        H.h[j] = __float2half_rn(vv[j]);
        L.h[j] = __float2half_rn(vv[j] - __half2float(H.h[j]));
    }
    ((uint2*)hi)[off] = H.u;
    ((uint2*)lo)[off] = L.u;
}

// ---------------------------------------------------------------------------
// HMMA fp16x2 GEMM: out[M,N] = A_fp16[M,K] @ (Wh+Wl)[N,K]^T + bias
// 128x128 CTA tile, BK=64, 8 warps (2x4) each 64x32, cp.async 2-stage.
// Stage: A 16KB + Bh 16KB + Bl 16KB = 48KB; 2 stages = 96KB -> 2 CTAs/SM.
// blockIdx.z selects among up to 3 (W, bias, out) sets (fused Q/K/V).
// ---------------------------------------------------------------------------
constexpr int BKg = 64;
constexpr int NKC = Dm / BKg;                  // 16
constexpr int ATILE = 128 * 128;               // 16 KB
constexpr int STAGE_BYTES = 3 * ATILE;         // 48 KB
constexpr int GEMM_SMEM = 2 * STAGE_BYTES;     // 96 KB

template <bool SPLIT>
__global__ __launch_bounds__(256, 2) void hmma_gemm_kernel(
    const __half* __restrict__ Af,
    const __half* __restrict__ Bh0, const __half* __restrict__ Bh1,
    const __half* __restrict__ Bh2,
    const __half* __restrict__ Bl0, const __half* __restrict__ Bl1,
    const __half* __restrict__ Bl2,
    const float* __restrict__ bias0, const float* __restrict__ bias1,
    const float* __restrict__ bias2,
    float* __restrict__ outF,
    __nv_bfloat16* __restrict__ oh0, __nv_bfloat16* __restrict__ oh1,
    __nv_bfloat16* __restrict__ oh2,
    __nv_bfloat16* __restrict__ ol0, __nv_bfloat16* __restrict__ ol1,
    __nv_bfloat16* __restrict__ ol2)
{
    extern __shared__ char sm[];
    const uint32_t smb = smem_u32(sm);
    const int z    = blockIdx.z;
    const __half* Bh = z == 0 ? Bh0 : z == 1 ? Bh1 : Bh2;
    const __half* Bl = z == 0 ? Bl0 : z == 1 ? Bl1 : Bl2;
    const float* bias       = z == 0 ? bias0 : z == 1 ? bias1 : bias2;
    __nv_bfloat16* outH     = z == 0 ? oh0 : z == 1 ? oh1 : oh2;
    __nv_bfloat16* outL     = z == 0 ? ol0 : z == 1 ? ol1 : ol2;
    const float scale = (SPLIT && z == 0) ? 0.125f : 1.0f;

    const int t    = threadIdx.x;
    const int wid  = t >> 5;
    const int lane = t & 31;
    const int m0   = blockIdx.y * 128;
    const int n0   = blockIdx.x * 128;
    const int wm   = (wid & 1) * 64;
    const int wn   = (wid >> 1) * 32;

    // One stage: A (16KB) | Bh (16KB) | Bl (16KB). 128 rows x 128B each (BK=64 fp16).
    auto load_stage = [&](int s, int kc) {
        const uint32_t ab  = smb + s * STAGE_BYTES;
        const uint32_t bhb = ab + ATILE;
        const uint32_t blb = ab + 2 * ATILE;
#pragma unroll
        for (int i = 0; i < 4; i++) {
            const int idx = t + i * 256;        // 0..1023
            const int row = idx >> 3;
            const int c   = idx & 7;
            const int kofs = kc * BKg + c * 8;  // 8 fp16 per 16B
            cp16(ab  + swz(row, c), Af + (size_t)(m0 + row) * Dm + kofs);
            cp16(bhb + swz(row, c), Bh + (size_t)(n0 + row) * Dm + kofs);
            cp16(blb + swz(row, c), Bl + (size_t)(n0 + row) * Dm + kofs);
        }
        CP_COMMIT();
    };

    float acc[4][4][4];
#pragma unroll
    for (int i = 0; i < 4; i++)
#pragma unroll
        for (int j = 0; j < 4; j++)
#pragma unroll
            for (int r = 0; r < 4; r++) acc[i][j][r] = 0.0f;

    load_stage(0, 0);

    const int lrow = lane & 15;
    const int lsel = lane >> 4;

    int s = 0;
    for (int kc = 0; kc < NKC; kc++) {
        CP_WAIT(0);
        __syncthreads();                 // all warps done with stage s^1
        if (kc + 1 < NKC) load_stage(s ^ 1, kc + 1);   // overlaps compute below

        const uint32_t ab  = smb + s * STAGE_BYTES;
        const uint32_t bhb = ab + ATILE;
        const uint32_t blb = ab + 2 * ATILE;

#pragma unroll
        for (int k16 = 0; k16 < 4; k16++) {
            const int ch = k16 * 2 + lsel;   // 0..7
            uint32_t a_f[4][4];
#pragma unroll
            for (int mt = 0; mt < 4; mt++)
                ldm_x4(a_f[mt], ab + swz(wm + mt * 16 + lrow, ch));
            uint32_t b_h[2][4], b_l[2][4];
#pragma unroll
            for (int nt = 0; nt < 2; nt++) {
                const int row = wn + nt * 16 + lrow;
                ldm_x4(b_h[nt], bhb + swz(row, ch));
                ldm_x4(b_l[nt], blb + swz(row, ch));
            }
#pragma unroll
            for (int mt = 0; mt < 4; mt++) {
#pragma unroll
                for (int n8 = 0; n8 < 4; n8++) {
                    const int nt = n8 >> 1, sl = n8 & 1;
                    mma_fp16(acc[mt][n8], a_f[mt], b_h[nt][sl], b_h[nt][sl + 2]);
                    mma_fp16(acc[mt][n8], a_f[mt], b_l[nt][sl], b_l[nt][sl + 2]);
                }
            }
        }
        s ^= 1;
    }

#pragma unroll
    for (int mt = 0; mt < 4; mt++) {
#pragma unroll
        for (int n8 = 0; n8 < 4; n8++) {
            const int r0 = m0 + wm + mt * 16 + (lane >> 2);
            const int c0 = n0 + wn + n8 * 8 + (lane & 3) * 2;
#pragma unroll
            for (int half = 0; half < 2; half++) {
                const int m = r0 + half * 8;
                const int b_ = m / Sq;
                const int s_ = m % Sq;
                const float v0 = (acc[mt][n8][half * 2 + 0] + bias[c0]) * scale;
                const float v1 = (acc[mt][n8][half * 2 + 1] + bias[c0 + 1]) * scale;
                if (SPLIT) {
                    const int h_ = c0 >> 6;
                    const int d_ = c0 & 63;
                    const size_t off =
                        ((((size_t)(b_ * Hh + h_)) * Sq + s_) * HDd + d_) >> 1;
                    ((uint32_t*)outH)[off] = bf2(v0, v1);
                    ((uint32_t*)outL)[off] = bf2(v0 - bf16rt(v0), v1 - bf16rt(v1));
                } else {
                    float* dst = outF + (size_t)m * Dm + c0;
                    dst[0] = v0; dst[1] = v1;
                }
            }
        }
    }
}

// ---------------------------------------------------------------------------
// HMMA flash attention (round-6 config): CTA = (64 queries, head, batch),
// 4 warps x 16 rows, 3 CTAs/SM. K double-buffered, V single-buffered.
// ctx written as fp16 (single buffer) for the fp16x2 output projection.
// Longest CTAs first: qt = gridDim.x - 1 - blockIdx.x.
// ---------------------------------------------------------------------------
constexpr int FA_Q    = 16384;
constexpr int FA_KST  = 16384;                 // one K stage (hi+lo)
constexpr int FA_VOFF = FA_Q + 2 * FA_KST;     // 49152
constexpr int FA_MOFF = FA_VOFF + 16384;       // 65536
constexpr int FA_SMEM = FA_MOFF + 512;         // 66048

__global__ __launch_bounds__(128, 3) void fa_hmma_kernel(
    const __nv_bfloat16* __restrict__ Qh, const __nv_bfloat16* __restrict__ Ql,
    const __nv_bfloat16* __restrict__ Kh, const __nv_bfloat16* __restrict__ Kl,
    const __nv_bfloat16* __restrict__ Vh, const __nv_bfloat16* __restrict__ Vl,
    const int* __restrict__ maskg,
    __half* __restrict__ Cf)
{
    extern __shared__ char sm[];
    const uint32_t smb = smem_u32(sm);
    const int t    = threadIdx.x;
    const int w    = t >> 5;
    const int lane = t & 31;
    const int qt   = gridDim.x - 1 - blockIdx.x;   // longest-first
    const int h    = blockIdx.y;
    const int b    = blockIdx.z;
    const size_t hb = ((size_t)(b * Hh + h)) * Sq * HDd;

    const uint32_t qhb = smb;
    const uint32_t qlb = smb + 8192;
    const uint32_t vhb = smb + FA_VOFF;
    const uint32_t vlb = smb + FA_VOFF + 8192;

    auto load_k = [&](int s, int kt2) {
        const uint32_t kb = smb + FA_Q + s * FA_KST;
        const char* sKH = (const char*)(Kh + hb + (size_t)kt2 * 64 * HDd);
        const char* sKL = (const char*)(Kl + hb + (size_t)kt2 * 64 * HDd);
#pragma unroll
        for (int i = 0; i < 4; i++) {
            const int idx = t + i * 128;
            const int row = idx >> 3, c = idx & 7;
            cp16(kb + swz(row, c), sKH + idx * 16);
            cp16(kb + 8192 + swz(row, c), sKL + idx * 16);
        }
        if (t < 16) cp16(smb + FA_MOFF + s * 256 + t * 16,
                         maskg + b * Sq + kt2 * 64 + t * 4);
        CP_COMMIT();
    };
    auto load_v = [&](int kt2) {
        const char* sVH = (const char*)(Vh + hb + (size_t)kt2 * 64 * HDd);
        const char* sVL = (const char*)(Vl + hb + (size_t)kt2 * 64 * HDd);
#pragma unroll
        for (int i = 0; i < 4; i++) {
            const int idx = t + i * 128;
            const int row = idx >> 3, c = idx & 7;
            cp16(vhb + swz(row, c), sVH + idx * 16);
            cp16(vlb + swz(row, c), sVL + idx * 16);
        }
        CP_COMMIT();
    };

    // Prologue: Q tile + K(0) + mask(0) in one group.
    {
        const char* srcH = (const char*)(Qh + hb + (size_t)qt * 64 * HDd);
        const char* srcL = (const char*)(Ql + hb + (size_t)qt * 64 * HDd);
#pragma unroll
        for (int i = 0; i < 4; i++) {
            const int idx = t + i * 128;
            const int row = idx >> 3, c = idx & 7;
            cp16(qhb + swz(row, c), srcH + idx * 16);
            cp16(qlb + swz(row, c), srcL + idx * 16);
        }
    }
    load_k(0, 0);

    const int lrow  = lane & 15;
    const int lsel  = lane >> 4;
    const int rl    = lane >> 2;
    const int cbase = (lane & 3) * 2;
    const int wr0   = w * 16;

    float m_i[2] = {-INFINITY, -INFINITY};
    float l_i[2] = {0.0f, 0.0f};
    float o[8][4];
#pragma unroll
    for (int n8 = 0; n8 < 8; n8++)
#pragma unroll
        for (int c = 0; c < 4; c++) o[n8][c] = 0.0f;

    for (int kt2 = 0; kt2 <= qt; kt2++) {
        const int s = kt2 & 1;

        __syncthreads();            // V buffer free (PV of prev tile done)
        load_v(kt2);                // completes under S/softmax below
        if (kt2 < qt) { load_k(s ^ 1, kt2 + 1); CP_WAIT(2); }
        else          { CP_WAIT(1); }
        __syncthreads();            // K(kt2)+mask visible to all warps

        const uint32_t khb = smb + FA_Q + s * FA_KST;
        const uint32_t klb = khb + 8192;
        const int* msk = (const int*)(sm + FA_MOFF + s * 256);

        // ---- S = Q @ K^T (bf16x3) ----
        float sc[8][4];
#pragma unroll
        for (int n8 = 0; n8 < 8; n8++)
#pragma unroll
            for (int c = 0; c < 4; c++) sc[n8][c] = 0.0f;

#pragma unroll
        for (int k16 = 0; k16 < 4; k16++) {
            const int ch = k16 * 2 + lsel;
            uint32_t qf_h[4], qf_l[4];
            ldm_x4(qf_h, qhb + swz(wr0 + lrow, ch));
            ldm_x4(qf_l, qlb + swz(wr0 + lrow, ch));
            uint32_t kf_h[4][4], kf_l[4][4];
#pragma unroll
            for (int nt = 0; nt < 4; nt++) {
                ldm_x4(kf_h[nt], khb + swz(nt * 16 + lrow, ch));
                ldm_x4(kf_l[nt], klb + swz(nt * 16 + lrow, ch));
            }
#pragma unroll
            for (int n8 = 0; n8 < 8; n8++) {
                const int nt = n8 >> 1, sl = n8 & 1;
                mma_bf16(sc[n8], qf_h, kf_h[nt][sl], kf_h[nt][sl + 2]);
                mma_bf16(sc[n8], qf_h, kf_l[nt][sl], kf_l[nt][sl + 2]);
                mma_bf16(sc[n8], qf_l, kf_h[nt][sl], kf_h[nt][sl + 2]);
            }
        }

        // ---- masking (pad overrides causal, reference order) ----
        const bool diag = (kt2 == qt);
        const int qi0 = qt * 64 + wr0 + rl;
#pragma unroll
        for (int n8 = 0; n8 < 8; n8++) {
#pragma unroll
            for (int c = 0; c < 4; c++) {
                const int colL = n8 * 8 + cbase + (c & 1);
                const int mv = msk[colL];
                if (mv == 0) sc[n8][c] = -1e9f;
                else if (diag) {
                    const int kj = kt2 * 64 + colL;
                    const int qi = qi0 + (c >> 1) * 8;
                    if (kj > qi) sc[n8][c] = -INFINITY;
                }
            }
        }

        // ---- online softmax (rows rl, rl+8) ----
#pragma unroll
        for (int r = 0; r < 2; r++) {
            float mx = -INFINITY;
#pragma unroll
            for (int n8 = 0; n8 < 8; n8++)
                mx = fmaxf(mx, fmaxf(sc[n8][2 * r], sc[n8][2 * r + 1]));
            mx = fmaxf(mx, __shfl_xor_sync(0xffffffffu, mx, 1));
            mx = fmaxf(mx, __shfl_xor_sync(0xffffffffu, mx, 2));
            const float mnew  = fmaxf(m_i[r], mx);
            const float alpha = __expf(m_i[r] - mnew);
            float sum = 0.0f;
#pragma unroll
            for (int n8 = 0; n8 < 8; n8++) {
                const float p0 = __expf(sc[n8][2 * r]     - mnew);
                const float p1 = __expf(sc[n8][2 * r + 1] - mnew);
                sc[n8][2 * r] = p0; sc[n8][2 * r + 1] = p1;
                sum += p0 + p1;
            }
            sum += __shfl_xor_sync(0xffffffffu, sum, 1);
            sum += __shfl_xor_sync(0xffffffffu, sum, 2);
            l_i[r] = l_i[r] * alpha + sum;
            m_i[r] = mnew;
#pragma unroll
            for (int n8 = 0; n8 < 8; n8++) {
                o[n8][2 * r] *= alpha; o[n8][2 * r + 1] *= alpha;
            }
        }

        // ---- P -> bf16 hi/lo A-fragments ----
        uint32_t pah[4][4], pal[4][4];
#pragma unroll
        for (int j = 0; j < 4; j++) {
#pragma unroll
            for (int u = 0; u < 4; u++) {
                const int tile = 2 * j + (u >> 1);
                const int ci   = (u & 1) * 2;
                const float p0 = sc[tile][ci], p1 = sc[tile][ci + 1];
                pah[j][u] = bf2(p0, p1);
                pal[j][u] = bf2(p0 - bf16rt(p0), p1 - bf16rt(p1));
            }
        }

        // ---- wait V(kt2), then O += P @ V (bf16x3) ----
        if (kt2 < qt) { CP_WAIT(1); } else { CP_WAIT(0); }
        __syncthreads();            // V visible to all warps

#pragma unroll
        for (int j = 0; j < 4; j++) {
            const int mrow = 16 * j + ((lane >> 3) & 1) * 8 + (lane & 7);
            uint32_t vf_h[4][4], vf_l[4][4];
#pragma unroll
            for (int hp = 0; hp < 4; hp++) {
                const int chv = hp * 2 + (lane >> 4);
                ldm_x4_t(vf_h[hp], vhb + swz(mrow, chv));
                ldm_x4_t(vf_l[hp], vlb + swz(mrow, chv));
            }
#pragma unroll
            for (int n8 = 0; n8 < 8; n8++) {
                const int hp = n8 >> 1, q_ = n8 & 1;
                mma_bf16(o[n8], pah[j], vf_h[hp][2 * q_], vf_h[hp][2 * q_ + 1]);
                mma_bf16(o[n8], pal[j], vf_h[hp][2 * q_], vf_h[hp][2 * q_ + 1]);
                mma_bf16(o[n8], pah[j], vf_l[hp][2 * q_], vf_l[hp][2 * q_ + 1]);
            }
        }
    }

    // ---- normalize + write ctx fp16 [B,S,D] ----
#pragma unroll
    for (int r = 0; r < 2; r++) {
        const float inv = 1.0f / l_i[r];
        const int m = qt * 64 + wr0 + rl + r * 8;
        const size_t rowoff = ((size_t)b * Sq + m) * Dm + h * HDd;
#pragma unroll
        for (int n8 = 0; n8 < 8; n8++) {
            const int col = n8 * 8 + cbase;
            __half2 hv = __floats2half2_rn(o[n8][2 * r] * inv, o[n8][2 * r + 1] * inv);
            *((__half2*)(Cf + rowoff + col)) = hv;
        }
    }
}

// ---------------------------------------------------------------------------
// Launch
// ---------------------------------------------------------------------------
extern "C" void kernel_launch(void* const* d_in, const int* in_sizes, int n_in,
                              void* d_out, int out_size)
{
    const float* x  = nullptr;
    const int*   am = nullptr;
    const float* Ws[4] = {nullptr, nullptr, nullptr, nullptr};
    const float* bs[4] = {nullptr, nullptr, nullptr, nullptr};
    int wi = 0, bi = 0;
    for (int i = 0; i < n_in; i++) {
        const long sz = in_sizes[i];
        if (sz == (long)Mtot * Dm)      x = (const float*)d_in[i];
        else if (sz == (long)Mtot)      am = (const int*)d_in[i];
        else if (sz == (long)Dm * Dm) { if (wi < 4) Ws[wi++] = (const float*)d_in[i]; }
        else if (sz == (long)Dm)      { if (bi < 4) bs[bi++] = (const float*)d_in[i]; }
    }

    __half *xf, *wh, *wl, *cf;
    __nv_bfloat16 *qh, *ql, *kh, *kl, *vh, *vl;
    cudaGetSymbolAddress((void**)&xf, g_xf);
    cudaGetSymbolAddress((void**)&wh, g_wh);
    cudaGetSymbolAddress((void**)&wl, g_wl);
    cudaGetSymbolAddress((void**)&cf, g_cf);
    cudaGetSymbolAddress((void**)&qh, g_qh);
    cudaGetSymbolAddress((void**)&ql, g_ql);
    cudaGetSymbolAddress((void**)&kh, g_kh);
    cudaGetSymbolAddress((void**)&kl, g_kl);
    cudaGetSymbolAddress((void**)&vh, g_vh);
    cudaGetSymbolAddress((void**)&vl, g_vl);

    cudaFuncSetAttribute(hmma_gemm_kernel<true>,
                         cudaFuncAttributeMaxDynamicSharedMemorySize, GEMM_SMEM);
    cudaFuncSetAttribute(hmma_gemm_kernel<false>,
                         cudaFuncAttributeMaxDynamicSharedMemorySize, GEMM_SMEM);
    cudaFuncSetAttribute(fa_hmma_kernel,
                         cudaFuncAttributeMaxDynamicSharedMemorySize, FA_SMEM);

    // Conversions
    const int n4x = Mtot * Dm / 4;
    const int n4w = Dm * Dm / 4;
    cvt_x_kernel<<<(n4x + 255) / 256, 256>>>(x, xf, n4x);
    cvt_w_kernel<<<dim3((n4w + 255) / 256, 4), 256>>>(
        Ws[0], Ws[1], Ws[2], Ws[3], wh, wl);

    const size_t WSZ = (size_t)Dm * Dm;

    // Fused Q/K/V projections (fp16x2), Q carries softmax scale
    const dim3 gqkv(Dm / 128, Mtot / 128, 3);
    hmma_gemm_kernel<true><<<gqkv, 256, GEMM_SMEM>>>(
        xf,
        wh + 0 * WSZ, wh + 1 * WSZ, wh + 2 * WSZ,
        wl + 0 * WSZ, wl + 1 * WSZ, wl + 2 * WSZ,
        bs[0], bs[1], bs[2],
        nullptr,
        qh, kh, vh,
        ql, kl, vl);

    // Attention (bf16x3, round-6 config, longest-first)
    const dim3 ga(Sq / 64, Hh, Bc);
    fa_hmma_kernel<<<ga, 128, FA_SMEM>>>(qh, ql, kh, kl, vh, vl, am, cf);

    // Output projection (fp16x2)
    const dim3 gg(Dm / 128, Mtot / 128, 1);
    hmma_gemm_kernel<false><<<gg, 256, GEMM_SMEM>>>(
        cf,
        wh + 3 * WSZ, wh + 3 * WSZ, wh + 3 * WSZ,
        wl + 3 * WSZ, wl + 3 * WSZ, wl + 3 * WSZ,
        bs[3], bs[3], bs[3],
        (float*)d_out,
        nullptr, nullptr, nullptr,
        nullptr, nullptr, nullptr);
}

// round 9
// speedup vs baseline: 1.5126x; 1.1297x over previous
#include <cuda_runtime.h>
#include <cuda_fp16.h>
#include <math.h>
#include <stdint.h>

// Problem constants
constexpr int Bc  = 4;
constexpr int Sq  = 2048;
constexpr int Dm  = 1024;
constexpr int Hh  = 16;
constexpr int HDd = 64;
constexpr int Mtot = Bc * Sq;           // 8192

// Scratch (device globals: allocation-free per harness rules)
__device__ __half g_xf[(size_t)Mtot * Dm];            // x fp16
__device__ __half g_wh[(size_t)4 * Dm * Dm];          // W hi fp16
__device__ __half g_wl[(size_t)4 * Dm * Dm];          // W lo fp16
__device__ __half g_cf[(size_t)Mtot * Dm];            // ctx fp16
__device__ __half g_qf[(size_t)Mtot * Dm];            // Q fp16 (single)
__device__ __half g_kh[(size_t)Mtot * Dm];
__device__ __half g_kl[(size_t)Mtot * Dm];
__device__ __half g_vh[(size_t)Mtot * Dm];
__device__ __half g_vl[(size_t)Mtot * Dm];

// ---------------------------------------------------------------------------
// PTX helpers
// ---------------------------------------------------------------------------
__device__ __forceinline__ uint32_t smem_u32(const void* p) {
    uint32_t a;
    asm("{ .reg .u64 t; cvta.to.shared.u64 t, %1; cvt.u32.u64 %0, t; }" : "=r"(a) : "l"(p));
    return a;
}
__device__ __forceinline__ void ldm_x4(uint32_t (&r)[4], uint32_t saddr) {
    asm volatile("ldmatrix.sync.aligned.m8n8.x4.shared.b16 {%0,%1,%2,%3}, [%4];"
        : "=r"(r[0]), "=r"(r[1]), "=r"(r[2]), "=r"(r[3]) : "r"(saddr));
}
__device__ __forceinline__ void ldm_x4_t(uint32_t (&r)[4], uint32_t saddr) {
    asm volatile("ldmatrix.sync.aligned.m8n8.x4.trans.shared.b16 {%0,%1,%2,%3}, [%4];"
        : "=r"(r[0]), "=r"(r[1]), "=r"(r[2]), "=r"(r[3]) : "r"(saddr));
}
__device__ __forceinline__ void mma_fp16(float (&c)[4], const uint32_t (&a)[4],
                                         uint32_t b0, uint32_t b1) {
    asm volatile("mma.sync.aligned.m16n8k16.row.col.f32.f16.f16.f32 "
        "{%0,%1,%2,%3}, {%4,%5,%6,%7}, {%8,%9}, {%0,%1,%2,%3};"
        : "+f"(c[0]), "+f"(c[1]), "+f"(c[2]), "+f"(c[3])
        : "r"(a[0]), "r"(a[1]), "r"(a[2]), "r"(a[3]), "r"(b0), "r"(b1));
}
__device__ __forceinline__ void cp16(uint32_t dst, const void* src) {
    asm volatile("cp.async.cg.shared.global [%0], [%1], 16;" :: "r"(dst), "l"(src) : "memory");
}
#define CP_COMMIT() asm volatile("cp.async.commit_group;" ::: "memory")
#define CP_WAIT(n)  asm volatile("cp.async.wait_group %0;" :: "n"(n) : "memory")

__device__ __forceinline__ uint32_t hf2(float a, float b) {
    __half2 t = __floats2half2_rn(a, b);
    return *reinterpret_cast<uint32_t*>(&t);
}
__device__ __forceinline__ float hf16rt(float a) {
    return __half2float(__float2half_rn(a));
}
__device__ __forceinline__ uint32_t swz(int row, int chunk) {
    return (uint32_t)(row * 128 + ((chunk ^ (row & 7)) * 16));
}

// ---------------------------------------------------------------------------
// Conversions: x -> fp16; weights -> fp16 hi/lo (y-indexed over 4 weights)
// ---------------------------------------------------------------------------
__global__ __launch_bounds__(256) void cvt_x_kernel(const float* __restrict__ in,
                                                    __half* __restrict__ out, int n4)
{
    const int i = blockIdx.x * blockDim.x + threadIdx.x;
    if (i >= n4) return;
    const float4 v = ((const float4*)in)[i];
    uint2 u;
    u.x = hf2(v.x, v.y);
    u.y = hf2(v.z, v.w);
    ((uint2*)out)[i] = u;
}

__global__ __launch_bounds__(256) void cvt_w_kernel(
    const float* __restrict__ w0, const float* __restrict__ w1,
    const float* __restrict__ w2, const float* __restrict__ w3,
    __half* __restrict__ hi, __half* __restrict__ lo)
{
    const int n4 = Dm * Dm / 4;
    const int i = blockIdx.x * blockDim.x + threadIdx.x;
    if (i >= n4) return;
    const int wsel = blockIdx.y;
    const float* in = wsel == 0 ? w0 : wsel == 1 ? w1 : wsel == 2 ? w2 : w3;
    const size_t off = (size_t)wsel * n4 + i;
    const float4 v = ((const float4*)in)[i];
    union { __half h[4]; uint2 u; } H, L;
    const float vv[4] = {v.x, v.y, v.z, v.w};
#pragma unroll
    for (int j = 0; j < 4; j++) {
        H.h[j] = __float2half_rn(vv[j]);
        L.h[j] = __float2half_rn(vv[j] - __half2float(H.h[j]));
    }
    ((uint2*)hi)[off] = H.u;
    ((uint2*)lo)[off] = L.u;
}

// ---------------------------------------------------------------------------
// HMMA fp16x2 GEMM: out[M,N] = A_fp16[M,K] @ (Wh+Wl)[N,K]^T + bias
// 128x128 CTA tile, BK=64, 8 warps (2x4), cp.async 2-stage (96KB).
// SPLIT=true: z==0 writes single fp16 (Q); z==1/2 write fp16 hi/lo (K/V),
// all in [B,H,S,HD]. SPLIT=false: f32 [M,N].
// ---------------------------------------------------------------------------
constexpr int BKg = 64;
constexpr int NKC = Dm / BKg;                  // 16
constexpr int ATILE = 128 * 128;               // 16 KB
constexpr int STAGE_BYTES = 3 * ATILE;         // 48 KB
constexpr int GEMM_SMEM = 2 * STAGE_BYTES;     // 96 KB

template <bool SPLIT>
__global__ __launch_bounds__(256, 2) void hmma_gemm_kernel(
    const __half* __restrict__ Af,
    const __half* __restrict__ Bh0, const __half* __restrict__ Bh1,
    const __half* __restrict__ Bh2,
    const __half* __restrict__ Bl0, const __half* __restrict__ Bl1,
    const __half* __restrict__ Bl2,
    const float* __restrict__ bias0, const float* __restrict__ bias1,
    const float* __restrict__ bias2,
    float* __restrict__ outF,
    __half* __restrict__ oh0, __half* __restrict__ oh1,
    __half* __restrict__ oh2,
    __half* __restrict__ ol0, __half* __restrict__ ol1,
    __half* __restrict__ ol2)
{
    extern __shared__ char sm[];
    const uint32_t smb = smem_u32(sm);
    const int z    = blockIdx.z;
    const __half* Bh = z == 0 ? Bh0 : z == 1 ? Bh1 : Bh2;
    const __half* Bl = z == 0 ? Bl0 : z == 1 ? Bl1 : Bl2;
    const float* bias = z == 0 ? bias0 : z == 1 ? bias1 : bias2;
    __half* outH      = z == 0 ? oh0 : z == 1 ? oh1 : oh2;
    __half* outL      = z == 0 ? ol0 : z == 1 ? ol1 : ol2;
    const float scale = (SPLIT && z == 0) ? 0.125f : 1.0f;

    const int t    = threadIdx.x;
    const int wid  = t >> 5;
    const int lane = t & 31;
    const int m0   = blockIdx.y * 128;
    const int n0   = blockIdx.x * 128;
    const int wm   = (wid & 1) * 64;
    const int wn   = (wid >> 1) * 32;

    auto load_stage = [&](int s, int kc) {
        const uint32_t ab  = smb + s * STAGE_BYTES;
        const uint32_t bhb = ab + ATILE;
        const uint32_t blb = ab + 2 * ATILE;
#pragma unroll
        for (int i = 0; i < 4; i++) {
            const int idx = t + i * 256;
            const int row = idx >> 3;
            const int c   = idx & 7;
            const int kofs = kc * BKg + c * 8;
            cp16(ab  + swz(row, c), Af + (size_t)(m0 + row) * Dm + kofs);
            cp16(bhb + swz(row, c), Bh + (size_t)(n0 + row) * Dm + kofs);
            cp16(blb + swz(row, c), Bl + (size_t)(n0 + row) * Dm + kofs);
        }
        CP_COMMIT();
    };

    float acc[4][4][4];
#pragma unroll
    for (int i = 0; i < 4; i++)
#pragma unroll
        for (int j = 0; j < 4; j++)
#pragma unroll
            for (int r = 0; r < 4; r++) acc[i][j][r] = 0.0f;

    load_stage(0, 0);

    const int lrow = lane & 15;
    const int lsel = lane >> 4;

    int s = 0;
    for (int kc = 0; kc < NKC; kc++) {
        CP_WAIT(0);
        __syncthreads();
        if (kc + 1 < NKC) load_stage(s ^ 1, kc + 1);

        const uint32_t ab  = smb + s * STAGE_BYTES;
        const uint32_t bhb = ab + ATILE;
        const uint32_t blb = ab + 2 * ATILE;

#pragma unroll
        for (int k16 = 0; k16 < 4; k16++) {
            const int ch = k16 * 2 + lsel;
            uint32_t a_f[4][4];
#pragma unroll
            for (int mt = 0; mt < 4; mt++)
                ldm_x4(a_f[mt], ab + swz(wm + mt * 16 + lrow, ch));
            uint32_t b_h[2][4], b_l[2][4];
#pragma unroll
            for (int nt = 0; nt < 2; nt++) {
                const int row = wn + nt * 16 + lrow;
                ldm_x4(b_h[nt], bhb + swz(row, ch));
                ldm_x4(b_l[nt], blb + swz(row, ch));
            }
#pragma unroll
            for (int mt = 0; mt < 4; mt++) {
#pragma unroll
                for (int n8 = 0; n8 < 4; n8++) {
                    const int nt = n8 >> 1, sl = n8 & 1;
                    mma_fp16(acc[mt][n8], a_f[mt], b_h[nt][sl], b_h[nt][sl + 2]);
                    mma_fp16(acc[mt][n8], a_f[mt], b_l[nt][sl], b_l[nt][sl + 2]);
                }
            }
        }
        s ^= 1;
    }

#pragma unroll
    for (int mt = 0; mt < 4; mt++) {
#pragma unroll
        for (int n8 = 0; n8 < 4; n8++) {
            const int r0 = m0 + wm + mt * 16 + (lane >> 2);
            const int c0 = n0 + wn + n8 * 8 + (lane & 3) * 2;
#pragma unroll
            for (int half = 0; half < 2; half++) {
                const int m = r0 + half * 8;
                const int b_ = m / Sq;
                const int s_ = m % Sq;
                const float v0 = (acc[mt][n8][half * 2 + 0] + bias[c0]) * scale;
                const float v1 = (acc[mt][n8][half * 2 + 1] + bias[c0 + 1]) * scale;
                if (SPLIT) {
                    const int h_ = c0 >> 6;
                    const int d_ = c0 & 63;
                    const size_t off =
                        ((((size_t)(b_ * Hh + h_)) * Sq + s_) * HDd + d_) >> 1;
                    ((uint32_t*)outH)[off] = hf2(v0, v1);
                    if (outL)
                        ((uint32_t*)outL)[off] =
                            hf2(v0 - hf16rt(v0), v1 - hf16rt(v1));
                } else {
                    float* dst = outF + (size_t)m * Dm + c0;
                    dst[0] = v0; dst[1] = v1;
                }
            }
        }
    }
}

// ---------------------------------------------------------------------------
// HMMA fp16x2 flash attention: CTA = (64 queries, head, batch), 4 warps.
// Q single fp16 (8KB), K fp16 hi/lo double-buffered (2x16KB), V fp16 hi/lo
// single-buffered (16KB), mask 512B -> 56.5KB/CTA, target 4 CTAs/SM.
// QK^T: 2 passes (Qf*Kh + Qf*Kl). PV: 2 passes (P*Vh + P*Vl), P single fp16.
// Longest-first: qt = gridDim.x - 1 - blockIdx.x.
// ---------------------------------------------------------------------------
constexpr int FA_Q    = 8192;
constexpr int FA_KST  = 16384;
constexpr int FA_VOFF = FA_Q + 2 * FA_KST;     // 40960
constexpr int FA_MOFF = FA_VOFF + 16384;       // 57344
constexpr int FA_SMEM = FA_MOFF + 512;         // 57856

__global__ __launch_bounds__(128, 4) void fa_hmma_kernel(
    const __half* __restrict__ Qf,
    const __half* __restrict__ Kh, const __half* __restrict__ Kl,
    const __half* __restrict__ Vh, const __half* __restrict__ Vl,
    const int* __restrict__ maskg,
    __half* __restrict__ Cf)
{
    extern __shared__ char sm[];
    const uint32_t smb = smem_u32(sm);
    const int t    = threadIdx.x;
    const int w    = t >> 5;
    const int lane = t & 31;
    const int qt   = gridDim.x - 1 - blockIdx.x;   // longest-first
    const int h    = blockIdx.y;
    const int b    = blockIdx.z;
    const size_t hb = ((size_t)(b * Hh + h)) * Sq * HDd;

    const uint32_t qfb = smb;
    const uint32_t vhb = smb + FA_VOFF;
    const uint32_t vlb = smb + FA_VOFF + 8192;

    auto load_k = [&](int s, int kt2) {
        const uint32_t kb = smb + FA_Q + s * FA_KST;
        const char* sKH = (const char*)(Kh + hb + (size_t)kt2 * 64 * HDd);
        const char* sKL = (const char*)(Kl + hb + (size_t)kt2 * 64 * HDd);
#pragma unroll
        for (int i = 0; i < 4; i++) {
            const int idx = t + i * 128;
            const int row = idx >> 3, c = idx & 7;
            cp16(kb + swz(row, c), sKH + idx * 16);
            cp16(kb + 8192 + swz(row, c), sKL + idx * 16);
        }
        if (t < 16) cp16(smb + FA_MOFF + s * 256 + t * 16,
                         maskg + b * Sq + kt2 * 64 + t * 4);
        CP_COMMIT();
    };
    auto load_v = [&](int kt2) {
        const char* sVH = (const char*)(Vh + hb + (size_t)kt2 * 64 * HDd);
        const char* sVL = (const char*)(Vl + hb + (size_t)kt2 * 64 * HDd);
#pragma unroll
        for (int i = 0; i < 4; i++) {
            const int idx = t + i * 128;
            const int row = idx >> 3, c = idx & 7;
            cp16(vhb + swz(row, c), sVH + idx * 16);
            cp16(vlb + swz(row, c), sVL + idx * 16);
        }
        CP_COMMIT();
    };

    // Prologue: Q tile (single fp16) + K(0) + mask(0) in one group.
    {
        const char* srcQ = (const char*)(Qf + hb + (size_t)qt * 64 * HDd);
#pragma unroll
        for (int i = 0; i < 4; i++) {
            const int idx = t + i * 128;
            const int row = idx >> 3, c = idx & 7;
            cp16(qfb + swz(row, c), srcQ + idx * 16);
        }
    }
    load_k(0, 0);

    const int lrow  = lane & 15;
    const int lsel  = lane >> 4;
    const int rl    = lane >> 2;
    const int cbase = (lane & 3) * 2;
    const int wr0   = w * 16;

    float m_i[2] = {-INFINITY, -INFINITY};
    float l_i[2] = {0.0f, 0.0f};
    float o[8][4];
#pragma unroll
    for (int n8 = 0; n8 < 8; n8++)
#pragma unroll
        for (int c = 0; c < 4; c++) o[n8][c] = 0.0f;

    for (int kt2 = 0; kt2 <= qt; kt2++) {
        const int s = kt2 & 1;

        __syncthreads();            // V buffer free (PV of prev tile done)
        load_v(kt2);                // completes under S/softmax below
        if (kt2 < qt) { load_k(s ^ 1, kt2 + 1); CP_WAIT(2); }
        else          { CP_WAIT(1); }
        __syncthreads();            // K(kt2)+mask visible

        const uint32_t khb = smb + FA_Q + s * FA_KST;
        const uint32_t klb = khb + 8192;
        const int* msk = (const int*)(sm + FA_MOFF + s * 256);

        // ---- S = Q @ K^T (fp16x2: Qf*Kh + Qf*Kl) ----
        float sc[8][4];
#pragma unroll
        for (int n8 = 0; n8 < 8; n8++)
#pragma unroll
            for (int c = 0; c < 4; c++) sc[n8][c] = 0.0f;

#pragma unroll
        for (int k16 = 0; k16 < 4; k16++) {
            const int ch = k16 * 2 + lsel;
            uint32_t qf[4];
            ldm_x4(qf, qfb + swz(wr0 + lrow, ch));
            uint32_t kf_h[4][4], kf_l[4][4];
#pragma unroll
            for (int nt = 0; nt < 4; nt++) {
                ldm_x4(kf_h[nt], khb + swz(nt * 16 + lrow, ch));
                ldm_x4(kf_l[nt], klb + swz(nt * 16 + lrow, ch));
            }
#pragma unroll
            for (int n8 = 0; n8 < 8; n8++) {
                const int nt = n8 >> 1, sl = n8 & 1;
                mma_fp16(sc[n8], qf, kf_h[nt][sl], kf_h[nt][sl + 2]);
                mma_fp16(sc[n8], qf, kf_l[nt][sl], kf_l[nt][sl + 2]);
            }
        }

        // ---- masking (pad overrides causal, reference order) ----
        const bool diag = (kt2 == qt);
        const int qi0 = qt * 64 + wr0 + rl;
#pragma unroll
        for (int n8 = 0; n8 < 8; n8++) {
#pragma unroll
            for (int c = 0; c < 4; c++) {
                const int colL = n8 * 8 + cbase + (c & 1);
                const int mv = msk[colL];
                if (mv == 0) sc[n8][c] = -1e9f;
                else if (diag) {
                    const int kj = kt2 * 64 + colL;
                    const int qi = qi0 + (c >> 1) * 8;
                    if (kj > qi) sc[n8][c] = -INFINITY;
                }
            }
        }

        // ---- online softmax (rows rl, rl+8) ----
#pragma unroll
        for (int r = 0; r < 2; r++) {
            float mx = -INFINITY;
#pragma unroll
            for (int n8 = 0; n8 < 8; n8++)
                mx = fmaxf(mx, fmaxf(sc[n8][2 * r], sc[n8][2 * r + 1]));
            mx = fmaxf(mx, __shfl_xor_sync(0xffffffffu, mx, 1));
            mx = fmaxf(mx, __shfl_xor_sync(0xffffffffu, mx, 2));
            const float mnew  = fmaxf(m_i[r], mx);
            const float alpha = __expf(m_i[r] - mnew);
            float sum = 0.0f;
#pragma unroll
            for (int n8 = 0; n8 < 8; n8++) {
                const float p0 = __expf(sc[n8][2 * r]     - mnew);
                const float p1 = __expf(sc[n8][2 * r + 1] - mnew);
                sc[n8][2 * r] = p0; sc[n8][2 * r + 1] = p1;
                sum += p0 + p1;
            }
            sum += __shfl_xor_sync(0xffffffffu, sum, 1);
            sum += __shfl_xor_sync(0xffffffffu, sum, 2);
            l_i[r] = l_i[r] * alpha + sum;
            m_i[r] = mnew;
#pragma unroll
            for (int n8 = 0; n8 < 8; n8++) {
                o[n8][2 * r] *= alpha; o[n8][2 * r + 1] *= alpha;
            }
        }

        // ---- P -> single fp16 A-fragments ----
        uint32_t pa[4][4];
#pragma unroll
        for (int j = 0; j < 4; j++) {
#pragma unroll
            for (int u = 0; u < 4; u++) {
                const int tile = 2 * j + (u >> 1);
                const int ci   = (u & 1) * 2;
                pa[j][u] = hf2(sc[tile][ci], sc[tile][ci + 1]);
            }
        }

        // ---- wait V(kt2), then O += P @ V (fp16x2: P*Vh + P*Vl) ----
        if (kt2 < qt) { CP_WAIT(1); } else { CP_WAIT(0); }
        __syncthreads();            // V visible

#pragma unroll
        for (int j = 0; j < 4; j++) {
            const int mrow = 16 * j + ((lane >> 3) & 1) * 8 + (lane & 7);
            uint32_t vf_h[4][4], vf_l[4][4];
#pragma unroll
            for (int hp = 0; hp < 4; hp++) {
                const int chv = hp * 2 + (lane >> 4);
                ldm_x4_t(vf_h[hp], vhb + swz(mrow, chv));
                ldm_x4_t(vf_l[hp], vlb + swz(mrow, chv));
            }
#pragma unroll
            for (int n8 = 0; n8 < 8; n8++) {
                const int hp = n8 >> 1, q_ = n8 & 1;
                mma_fp16(o[n8], pa[j], vf_h[hp][2 * q_], vf_h[hp][2 * q_ + 1]);
                mma_fp16(o[n8], pa[j], vf_l[hp][2 * q_], vf_l[hp][2 * q_ + 1]);
            }
        }
    }

    // ---- normalize + write ctx fp16 [B,S,D] ----
#pragma unroll
    for (int r = 0; r < 2; r++) {
        const float inv = 1.0f / l_i[r];
        const int m = qt * 64 + wr0 + rl + r * 8;
        const size_t rowoff = ((size_t)b * Sq + m) * Dm + h * HDd;
#pragma unroll
        for (int n8 = 0; n8 < 8; n8++) {
            const int col = n8 * 8 + cbase;
            *((uint32_t*)(Cf + rowoff + col)) =
                hf2(o[n8][2 * r] * inv, o[n8][2 * r + 1] * inv);
        }
    }
}

// ---------------------------------------------------------------------------
// Launch
// ---------------------------------------------------------------------------
extern "C" void kernel_launch(void* const* d_in, const int* in_sizes, int n_in,
                              void* d_out, int out_size)
{
    const float* x  = nullptr;
    const int*   am = nullptr;
    const float* Ws[4] = {nullptr, nullptr, nullptr, nullptr};
    const float* bs[4] = {nullptr, nullptr, nullptr, nullptr};
    int wi = 0, bi = 0;
    for (int i = 0; i < n_in; i++) {
        const long sz = in_sizes[i];
        if (sz == (long)Mtot * Dm)      x = (const float*)d_in[i];
        else if (sz == (long)Mtot)      am = (const int*)d_in[i];
        else if (sz == (long)Dm * Dm) { if (wi < 4) Ws[wi++] = (const float*)d_in[i]; }
        else if (sz == (long)Dm)      { if (bi < 4) bs[bi++] = (const float*)d_in[i]; }
    }

    __half *xf, *wh, *wl, *cf, *qf, *kh, *kl, *vh, *vl;
    cudaGetSymbolAddress((void**)&xf, g_xf);
    cudaGetSymbolAddress((void**)&wh, g_wh);
    cudaGetSymbolAddress((void**)&wl, g_wl);
    cudaGetSymbolAddress((void**)&cf, g_cf);
    cudaGetSymbolAddress((void**)&qf, g_qf);
    cudaGetSymbolAddress((void**)&kh, g_kh);
    cudaGetSymbolAddress((void**)&kl, g_kl);
    cudaGetSymbolAddress((void**)&vh, g_vh);
    cudaGetSymbolAddress((void**)&vl, g_vl);

    cudaFuncSetAttribute(hmma_gemm_kernel<true>,
                         cudaFuncAttributeMaxDynamicSharedMemorySize, GEMM_SMEM);
    cudaFuncSetAttribute(hmma_gemm_kernel<false>,
                         cudaFuncAttributeMaxDynamicSharedMemorySize, GEMM_SMEM);
    cudaFuncSetAttribute(fa_hmma_kernel,
                         cudaFuncAttributeMaxDynamicSharedMemorySize, FA_SMEM);

    // Conversions
    const int n4x = Mtot * Dm / 4;
    const int n4w = Dm * Dm / 4;
    cvt_x_kernel<<<(n4x + 255) / 256, 256>>>(x, xf, n4x);
    cvt_w_kernel<<<dim3((n4w + 255) / 256, 4), 256>>>(
        Ws[0], Ws[1], Ws[2], Ws[3], wh, wl);

    const size_t WSZ = (size_t)Dm * Dm;

    // Fused Q/K/V projections (fp16x2); Q single fp16 (scale folded),
    // K/V as fp16 hi/lo.
    const dim3 gqkv(Dm / 128, Mtot / 128, 3);
    hmma_gemm_kernel<true><<<gqkv, 256, GEMM_SMEM>>>(
        xf,
        wh + 0 * WSZ, wh + 1 * WSZ, wh + 2 * WSZ,
        wl + 0 * WSZ, wl + 1 * WSZ, wl + 2 * WSZ,
        bs[0], bs[1], bs[2],
        nullptr,
        qf, kh, vh,
        nullptr, kl, vl);

    // Attention (fp16x2, 64-query tiles, target 4 CTAs/SM, longest-first)
    const dim3 ga(Sq / 64, Hh, Bc);
    fa_hmma_kernel<<<ga, 128, FA_SMEM>>>(qf, kh, kl, vh, vl, am, cf);

    // Output projection (fp16x2)
    const dim3 gg(Dm / 128, Mtot / 128, 1);
    hmma_gemm_kernel<false><<<gg, 256, GEMM_SMEM>>>(
        cf,
        wh + 3 * WSZ, wh + 3 * WSZ, wh + 3 * WSZ,
        wl + 3 * WSZ, wl + 3 * WSZ, wl + 3 * WSZ,
        bs[3], bs[3], bs[3],
        (float*)d_out,
        nullptr, nullptr, nullptr,
        nullptr, nullptr, nullptr);
}

// round 10
// speedup vs baseline: 1.5352x; 1.0150x over previous
#include <cuda_runtime.h>
#include <cuda_fp16.h>
#include <math.h>
#include <stdint.h>

// Problem constants
constexpr int Bc  = 4;
constexpr int Sq  = 2048;
constexpr int Dm  = 1024;
constexpr int Hh  = 16;
constexpr int HDd = 64;
constexpr int Mtot = Bc * Sq;           // 8192

// Scratch (device globals: allocation-free per harness rules)
__device__ __half g_xf[(size_t)Mtot * Dm];            // x fp16
__device__ __half g_wh[(size_t)4 * Dm * Dm];          // W hi fp16
__device__ __half g_wl[(size_t)4 * Dm * Dm];          // W lo fp16
__device__ __half g_cf[(size_t)Mtot * Dm];            // ctx fp16
__device__ __half g_qh[(size_t)Mtot * Dm];            // Q hi fp16
__device__ __half g_ql[(size_t)Mtot * Dm];            // Q lo fp16
__device__ __half g_kf[(size_t)Mtot * Dm];            // K single fp16
__device__ __half g_vh[(size_t)Mtot * Dm];
__device__ __half g_vl[(size_t)Mtot * Dm];

// ---------------------------------------------------------------------------
// PTX helpers
// ---------------------------------------------------------------------------
__device__ __forceinline__ uint32_t smem_u32(const void* p) {
    uint32_t a;
    asm("{ .reg .u64 t; cvta.to.shared.u64 t, %1; cvt.u32.u64 %0, t; }" : "=r"(a) : "l"(p));
    return a;
}
__device__ __forceinline__ void ldm_x4(uint32_t (&r)[4], uint32_t saddr) {
    asm volatile("ldmatrix.sync.aligned.m8n8.x4.shared.b16 {%0,%1,%2,%3}, [%4];"
        : "=r"(r[0]), "=r"(r[1]), "=r"(r[2]), "=r"(r[3]) : "r"(saddr));
}
__device__ __forceinline__ void ldm_x4_t(uint32_t (&r)[4], uint32_t saddr) {
    asm volatile("ldmatrix.sync.aligned.m8n8.x4.trans.shared.b16 {%0,%1,%2,%3}, [%4];"
        : "=r"(r[0]), "=r"(r[1]), "=r"(r[2]), "=r"(r[3]) : "r"(saddr));
}
__device__ __forceinline__ void mma_fp16(float (&c)[4], const uint32_t (&a)[4],
                                         uint32_t b0, uint32_t b1) {
    asm volatile("mma.sync.aligned.m16n8k16.row.col.f32.f16.f16.f32 "
        "{%0,%1,%2,%3}, {%4,%5,%6,%7}, {%8,%9}, {%0,%1,%2,%3};"
        : "+f"(c[0]), "+f"(c[1]), "+f"(c[2]), "+f"(c[3])
        : "r"(a[0]), "r"(a[1]), "r"(a[2]), "r"(a[3]), "r"(b0), "r"(b1));
}
__device__ __forceinline__ void cp16(uint32_t dst, const void* src) {
    asm volatile("cp.async.cg.shared.global [%0], [%1], 16;" :: "r"(dst), "l"(src) : "memory");
}
#define CP_COMMIT() asm volatile("cp.async.commit_group;" ::: "memory")
#define CP_WAIT(n)  asm volatile("cp.async.wait_group %0;" :: "n"(n) : "memory")

__device__ __forceinline__ uint32_t hf2(float a, float b) {
    __half2 t = __floats2half2_rn(a, b);
    return *reinterpret_cast<uint32_t*>(&t);
}
__device__ __forceinline__ float hf16rt(float a) {
    return __half2float(__float2half_rn(a));
}
__device__ __forceinline__ uint32_t swz(int row, int chunk) {
    return (uint32_t)(row * 128 + ((chunk ^ (row & 7)) * 16));
}

// ---------------------------------------------------------------------------
// Conversions: x -> fp16; weights -> fp16 hi/lo (y-indexed over 4 weights)
// ---------------------------------------------------------------------------
__global__ __launch_bounds__(256) void cvt_x_kernel(const float* __restrict__ in,
                                                    __half* __restrict__ out, int n4)
{
    const int i = blockIdx.x * blockDim.x + threadIdx.x;
    if (i >= n4) return;
    const float4 v = ((const float4*)in)[i];
    uint2 u;
    u.x = hf2(v.x, v.y);
    u.y = hf2(v.z, v.w);
    ((uint2*)out)[i] = u;
}

__global__ __launch_bounds__(256) void cvt_w_kernel(
    const float* __restrict__ w0, const float* __restrict__ w1,
    const float* __restrict__ w2, const float* __restrict__ w3,
    __half* __restrict__ hi, __half* __restrict__ lo)
{
    const int n4 = Dm * Dm / 4;
    const int i = blockIdx.x * blockDim.x + threadIdx.x;
    if (i >= n4) return;
    const int wsel = blockIdx.y;
    const float* in = wsel == 0 ? w0 : wsel == 1 ? w1 : wsel == 2 ? w2 : w3;
    const size_t off = (size_t)wsel * n4 + i;
    const float4 v = ((const float4*)in)[i];
    union { __half h[4]; uint2 u; } H, L;
    const float vv[4] = {v.x, v.y, v.z, v.w};
#pragma unroll
    for (int j = 0; j < 4; j++) {
        H.h[j] = __float2half_rn(vv[j]);
        L.h[j] = __float2half_rn(vv[j] - __half2float(H.h[j]));
    }
    ((uint2*)hi)[off] = H.u;
    ((uint2*)lo)[off] = L.u;
}

// ---------------------------------------------------------------------------
// HMMA fp16x2 GEMM: out[M,N] = A_fp16[M,K] @ (Wh+Wl)[N,K]^T + bias
// 128x128 CTA tile, BK=64, 8 warps (2x4), cp.async 2-stage (96KB).
// SPLIT=true: writes [B,H,S,HD]; outL==null -> single fp16, else hi/lo.
// SPLIT=false: f32 [M,N].
// ---------------------------------------------------------------------------
constexpr int BKg = 64;
constexpr int NKC = Dm / BKg;                  // 16
constexpr int ATILE = 128 * 128;               // 16 KB
constexpr int STAGE_BYTES = 3 * ATILE;         // 48 KB
constexpr int GEMM_SMEM = 2 * STAGE_BYTES;     // 96 KB

template <bool SPLIT>
__global__ __launch_bounds__(256, 2) void hmma_gemm_kernel(
    const __half* __restrict__ Af,
    const __half* __restrict__ Bh0, const __half* __restrict__ Bh1,
    const __half* __restrict__ Bh2,
    const __half* __restrict__ Bl0, const __half* __restrict__ Bl1,
    const __half* __restrict__ Bl2,
    const float* __restrict__ bias0, const float* __restrict__ bias1,
    const float* __restrict__ bias2,
    float* __restrict__ outF,
    __half* __restrict__ oh0, __half* __restrict__ oh1,
    __half* __restrict__ oh2,
    __half* __restrict__ ol0, __half* __restrict__ ol1,
    __half* __restrict__ ol2)
{
    extern __shared__ char sm[];
    const uint32_t smb = smem_u32(sm);
    const int z    = blockIdx.z;
    const __half* Bh = z == 0 ? Bh0 : z == 1 ? Bh1 : Bh2;
    const __half* Bl = z == 0 ? Bl0 : z == 1 ? Bl1 : Bl2;
    const float* bias = z == 0 ? bias0 : z == 1 ? bias1 : bias2;
    __half* outH      = z == 0 ? oh0 : z == 1 ? oh1 : oh2;
    __half* outL      = z == 0 ? ol0 : z == 1 ? ol1 : ol2;
    const float scale = (SPLIT && z == 0) ? 0.125f : 1.0f;

    const int t    = threadIdx.x;
    const int wid  = t >> 5;
    const int lane = t & 31;
    const int m0   = blockIdx.y * 128;
    const int n0   = blockIdx.x * 128;
    const int wm   = (wid & 1) * 64;
    const int wn   = (wid >> 1) * 32;

    auto load_stage = [&](int s, int kc) {
        const uint32_t ab  = smb + s * STAGE_BYTES;
        const uint32_t bhb = ab + ATILE;
        const uint32_t blb = ab + 2 * ATILE;
#pragma unroll
        for (int i = 0; i < 4; i++) {
            const int idx = t + i * 256;
            const int row = idx >> 3;
            const int c   = idx & 7;
            const int kofs = kc * BKg + c * 8;
            cp16(ab  + swz(row, c), Af + (size_t)(m0 + row) * Dm + kofs);
            cp16(bhb + swz(row, c), Bh + (size_t)(n0 + row) * Dm + kofs);
            cp16(blb + swz(row, c), Bl + (size_t)(n0 + row) * Dm + kofs);
        }
        CP_COMMIT();
    };

    float acc[4][4][4];
#pragma unroll
    for (int i = 0; i < 4; i++)
#pragma unroll
        for (int j = 0; j < 4; j++)
#pragma unroll
            for (int r = 0; r < 4; r++) acc[i][j][r] = 0.0f;

    load_stage(0, 0);

    const int lrow = lane & 15;
    const int lsel = lane >> 4;

    int s = 0;
    for (int kc = 0; kc < NKC; kc++) {
        CP_WAIT(0);
        __syncthreads();
        if (kc + 1 < NKC) load_stage(s ^ 1, kc + 1);

        const uint32_t ab  = smb + s * STAGE_BYTES;
        const uint32_t bhb = ab + ATILE;
        const uint32_t blb = ab + 2 * ATILE;

#pragma unroll
        for (int k16 = 0; k16 < 4; k16++) {
            const int ch = k16 * 2 + lsel;
            uint32_t a_f[4][4];
#pragma unroll
            for (int mt = 0; mt < 4; mt++)
                ldm_x4(a_f[mt], ab + swz(wm + mt * 16 + lrow, ch));
            uint32_t b_h[2][4], b_l[2][4];
#pragma unroll
            for (int nt = 0; nt < 2; nt++) {
                const int row = wn + nt * 16 + lrow;
                ldm_x4(b_h[nt], bhb + swz(row, ch));
                ldm_x4(b_l[nt], blb + swz(row, ch));
            }
#pragma unroll
            for (int mt = 0; mt < 4; mt++) {
#pragma unroll
                for (int n8 = 0; n8 < 4; n8++) {
                    const int nt = n8 >> 1, sl = n8 & 1;
                    mma_fp16(acc[mt][n8], a_f[mt], b_h[nt][sl], b_h[nt][sl + 2]);
                    mma_fp16(acc[mt][n8], a_f[mt], b_l[nt][sl], b_l[nt][sl + 2]);
                }
            }
        }
        s ^= 1;
    }

#pragma unroll
    for (int mt = 0; mt < 4; mt++) {
#pragma unroll
        for (int n8 = 0; n8 < 4; n8++) {
            const int r0 = m0 + wm + mt * 16 + (lane >> 2);
            const int c0 = n0 + wn + n8 * 8 + (lane & 3) * 2;
#pragma unroll
            for (int half = 0; half < 2; half++) {
                const int m = r0 + half * 8;
                const int b_ = m / Sq;
                const int s_ = m % Sq;
                const float v0 = (acc[mt][n8][half * 2 + 0] + bias[c0]) * scale;
                const float v1 = (acc[mt][n8][half * 2 + 1] + bias[c0 + 1]) * scale;
                if (SPLIT) {
                    const int h_ = c0 >> 6;
                    const int d_ = c0 & 63;
                    const size_t off =
                        ((((size_t)(b_ * Hh + h_)) * Sq + s_) * HDd + d_) >> 1;
                    ((uint32_t*)outH)[off] = hf2(v0, v1);
                    if (outL)
                        ((uint32_t*)outL)[off] =
                            hf2(v0 - hf16rt(v0), v1 - hf16rt(v1));
                } else {
                    float* dst = outF + (size_t)m * Dm + c0;
                    dst[0] = v0; dst[1] = v1;
                }
            }
        }
    }
}

// ---------------------------------------------------------------------------
// HMMA fp16x2 flash attention: CTA = (64 queries, head, batch), 4 warps.
// Q fp16 hi/lo (16KB, loaded once), K single fp16 double-buffered (2x8KB),
// V fp16 hi/lo single-buffered (16KB), mask 512B -> 48.5KB/CTA -> 4 CTAs/SM.
// QK^T: 2 passes (Qh*K + Ql*K). PV: 2 passes (P*Vh + P*Vl), P single fp16.
// Longest-first: qt = gridDim.x - 1 - blockIdx.x.
// ---------------------------------------------------------------------------
constexpr int FA_Q    = 16384;                 // Qh 8K + Ql 8K
constexpr int FA_KST  = 8192;                  // one K stage (single fp16)
constexpr int FA_VOFF = FA_Q + 2 * FA_KST;     // 32768
constexpr int FA_MOFF = FA_VOFF + 16384;       // 49152
constexpr int FA_SMEM = FA_MOFF + 512;         // 49664

__global__ __launch_bounds__(128, 4) void fa_hmma_kernel(
    const __half* __restrict__ Qh, const __half* __restrict__ Ql,
    const __half* __restrict__ Kf,
    const __half* __restrict__ Vh, const __half* __restrict__ Vl,
    const int* __restrict__ maskg,
    __half* __restrict__ Cf)
{
    extern __shared__ char sm[];
    const uint32_t smb = smem_u32(sm);
    const int t    = threadIdx.x;
    const int w    = t >> 5;
    const int lane = t & 31;
    const int qt   = gridDim.x - 1 - blockIdx.x;   // longest-first
    const int h    = blockIdx.y;
    const int b    = blockIdx.z;
    const size_t hb = ((size_t)(b * Hh + h)) * Sq * HDd;

    const uint32_t qhb = smb;
    const uint32_t qlb = smb + 8192;
    const uint32_t vhb = smb + FA_VOFF;
    const uint32_t vlb = smb + FA_VOFF + 8192;

    auto load_k = [&](int s, int kt2) {
        const uint32_t kb = smb + FA_Q + s * FA_KST;
        const char* sK = (const char*)(Kf + hb + (size_t)kt2 * 64 * HDd);
#pragma unroll
        for (int i = 0; i < 4; i++) {
            const int idx = t + i * 128;
            const int row = idx >> 3, c = idx & 7;
            cp16(kb + swz(row, c), sK + idx * 16);
        }
        if (t < 16) cp16(smb + FA_MOFF + s * 256 + t * 16,
                         maskg + b * Sq + kt2 * 64 + t * 4);
        CP_COMMIT();
    };
    auto load_v = [&](int kt2) {
        const char* sVH = (const char*)(Vh + hb + (size_t)kt2 * 64 * HDd);
        const char* sVL = (const char*)(Vl + hb + (size_t)kt2 * 64 * HDd);
#pragma unroll
        for (int i = 0; i < 4; i++) {
            const int idx = t + i * 128;
            const int row = idx >> 3, c = idx & 7;
            cp16(vhb + swz(row, c), sVH + idx * 16);
            cp16(vlb + swz(row, c), sVL + idx * 16);
        }
        CP_COMMIT();
    };

    // Prologue: Q tile hi/lo + K(0) + mask(0) in one group.
    {
        const char* srcH = (const char*)(Qh + hb + (size_t)qt * 64 * HDd);
        const char* srcL = (const char*)(Ql + hb + (size_t)qt * 64 * HDd);
#pragma unroll
        for (int i = 0; i < 4; i++) {
            const int idx = t + i * 128;
            const int row = idx >> 3, c = idx & 7;
            cp16(qhb + swz(row, c), srcH + idx * 16);
            cp16(qlb + swz(row, c), srcL + idx * 16);
        }
    }
    load_k(0, 0);

    const int lrow  = lane & 15;
    const int lsel  = lane >> 4;
    const int rl    = lane >> 2;
    const int cbase = (lane & 3) * 2;
    const int wr0   = w * 16;

    float m_i[2] = {-INFINITY, -INFINITY};
    float l_i[2] = {0.0f, 0.0f};
    float o[8][4];
#pragma unroll
    for (int n8 = 0; n8 < 8; n8++)
#pragma unroll
        for (int c = 0; c < 4; c++) o[n8][c] = 0.0f;

    for (int kt2 = 0; kt2 <= qt; kt2++) {
        const int s = kt2 & 1;

        __syncthreads();            // V buffer free (PV of prev tile done)
        load_v(kt2);                // completes under S/softmax below
        if (kt2 < qt) { load_k(s ^ 1, kt2 + 1); CP_WAIT(2); }
        else          { CP_WAIT(1); }
        __syncthreads();            // K(kt2)+mask visible

        const uint32_t kfb = smb + FA_Q + s * FA_KST;
        const int* msk = (const int*)(sm + FA_MOFF + s * 256);

        // ---- S = Q @ K^T (fp16x2: Qh*K + Ql*K) ----
        float sc[8][4];
#pragma unroll
        for (int n8 = 0; n8 < 8; n8++)
#pragma unroll
            for (int c = 0; c < 4; c++) sc[n8][c] = 0.0f;

#pragma unroll
        for (int k16 = 0; k16 < 4; k16++) {
            const int ch = k16 * 2 + lsel;
            uint32_t qf_h[4], qf_l[4];
            ldm_x4(qf_h, qhb + swz(wr0 + lrow, ch));
            ldm_x4(qf_l, qlb + swz(wr0 + lrow, ch));
            uint32_t kf[4][4];
#pragma unroll
            for (int nt = 0; nt < 4; nt++)
                ldm_x4(kf[nt], kfb + swz(nt * 16 + lrow, ch));
#pragma unroll
            for (int n8 = 0; n8 < 8; n8++) {
                const int nt = n8 >> 1, sl = n8 & 1;
                mma_fp16(sc[n8], qf_h, kf[nt][sl], kf[nt][sl + 2]);
                mma_fp16(sc[n8], qf_l, kf[nt][sl], kf[nt][sl + 2]);
            }
        }

        // ---- masking (pad overrides causal, reference order) ----
        const bool diag = (kt2 == qt);
        const int qi0 = qt * 64 + wr0 + rl;
#pragma unroll
        for (int n8 = 0; n8 < 8; n8++) {
#pragma unroll
            for (int c = 0; c < 4; c++) {
                const int colL = n8 * 8 + cbase + (c & 1);
                const int mv = msk[colL];
                if (mv == 0) sc[n8][c] = -1e9f;
                else if (diag) {
                    const int kj = kt2 * 64 + colL;
                    const int qi = qi0 + (c >> 1) * 8;
                    if (kj > qi) sc[n8][c] = -INFINITY;
                }
            }
        }

        // ---- online softmax (rows rl, rl+8) ----
#pragma unroll
        for (int r = 0; r < 2; r++) {
            float mx = -INFINITY;
#pragma unroll
            for (int n8 = 0; n8 < 8; n8++)
                mx = fmaxf(mx, fmaxf(sc[n8][2 * r], sc[n8][2 * r + 1]));
            mx = fmaxf(mx, __shfl_xor_sync(0xffffffffu, mx, 1));
            mx = fmaxf(mx, __shfl_xor_sync(0xffffffffu, mx, 2));
            const float mnew  = fmaxf(m_i[r], mx);
            const float alpha = __expf(m_i[r] - mnew);
            float sum = 0.0f;
#pragma unroll
            for (int n8 = 0; n8 < 8; n8++) {
                const float p0 = __expf(sc[n8][2 * r]     - mnew);
                const float p1 = __expf(sc[n8][2 * r + 1] - mnew);
                sc[n8][2 * r] = p0; sc[n8][2 * r + 1] = p1;
                sum += p0 + p1;
            }
            sum += __shfl_xor_sync(0xffffffffu, sum, 1);
            sum += __shfl_xor_sync(0xffffffffu, sum, 2);
            l_i[r] = l_i[r] * alpha + sum;
            m_i[r] = mnew;
#pragma unroll
            for (int n8 = 0; n8 < 8; n8++) {
                o[n8][2 * r] *= alpha; o[n8][2 * r + 1] *= alpha;
            }
        }

        // ---- P -> single fp16 A-fragments ----
        uint32_t pa[4][4];
#pragma unroll
        for (int j = 0; j < 4; j++) {
#pragma unroll
            for (int u = 0; u < 4; u++) {
                const int tile = 2 * j + (u >> 1);
                const int ci   = (u & 1) * 2;
                pa[j][u] = hf2(sc[tile][ci], sc[tile][ci + 1]);
            }
        }

        // ---- wait V(kt2), then O += P @ V (fp16x2: P*Vh + P*Vl) ----
        if (kt2 < qt) { CP_WAIT(1); } else { CP_WAIT(0); }
        __syncthreads();            // V visible

#pragma unroll
        for (int j = 0; j < 4; j++) {
            const int mrow = 16 * j + ((lane >> 3) & 1) * 8 + (lane & 7);
            uint32_t vf_h[4][4], vf_l[4][4];
#pragma unroll
            for (int hp = 0; hp < 4; hp++) {
                const int chv = hp * 2 + (lane >> 4);
                ldm_x4_t(vf_h[hp], vhb + swz(mrow, chv));
                ldm_x4_t(vf_l[hp], vlb + swz(mrow, chv));
            }
#pragma unroll
            for (int n8 = 0; n8 < 8; n8++) {
                const int hp = n8 >> 1, q_ = n8 & 1;
                mma_fp16(o[n8], pa[j], vf_h[hp][2 * q_], vf_h[hp][2 * q_ + 1]);
                mma_fp16(o[n8], pa[j], vf_l[hp][2 * q_], vf_l[hp][2 * q_ + 1]);
            }
        }
    }

    // ---- normalize + write ctx fp16 [B,S,D] ----
#pragma unroll
    for (int r = 0; r < 2; r++) {
        const float inv = 1.0f / l_i[r];
        const int m = qt * 64 + wr0 + rl + r * 8;
        const size_t rowoff = ((size_t)b * Sq + m) * Dm + h * HDd;
#pragma unroll
        for (int n8 = 0; n8 < 8; n8++) {
            const int col = n8 * 8 + cbase;
            *((uint32_t*)(Cf + rowoff + col)) =
                hf2(o[n8][2 * r] * inv, o[n8][2 * r + 1] * inv);
        }
    }
}

// ---------------------------------------------------------------------------
// Launch
// ---------------------------------------------------------------------------
extern "C" void kernel_launch(void* const* d_in, const int* in_sizes, int n_in,
                              void* d_out, int out_size)
{
    const float* x  = nullptr;
    const int*   am = nullptr;
    const float* Ws[4] = {nullptr, nullptr, nullptr, nullptr};
    const float* bs[4] = {nullptr, nullptr, nullptr, nullptr};
    int wi = 0, bi = 0;
    for (int i = 0; i < n_in; i++) {
        const long sz = in_sizes[i];
        if (sz == (long)Mtot * Dm)      x = (const float*)d_in[i];
        else if (sz == (long)Mtot)      am = (const int*)d_in[i];
        else if (sz == (long)Dm * Dm) { if (wi < 4) Ws[wi++] = (const float*)d_in[i]; }
        else if (sz == (long)Dm)      { if (bi < 4) bs[bi++] = (const float*)d_in[i]; }
    }

    __half *xf, *wh, *wl, *cf, *qh, *ql, *kf, *vh, *vl;
    cudaGetSymbolAddress((void**)&xf, g_xf);
    cudaGetSymbolAddress((void**)&wh, g_wh);
    cudaGetSymbolAddress((void**)&wl, g_wl);
    cudaGetSymbolAddress((void**)&cf, g_cf);
    cudaGetSymbolAddress((void**)&qh, g_qh);
    cudaGetSymbolAddress((void**)&ql, g_ql);
    cudaGetSymbolAddress((void**)&kf, g_kf);
    cudaGetSymbolAddress((void**)&vh, g_vh);
    cudaGetSymbolAddress((void**)&vl, g_vl);

    cudaFuncSetAttribute(hmma_gemm_kernel<true>,
                         cudaFuncAttributeMaxDynamicSharedMemorySize, GEMM_SMEM);
    cudaFuncSetAttribute(hmma_gemm_kernel<false>,
                         cudaFuncAttributeMaxDynamicSharedMemorySize, GEMM_SMEM);
    cudaFuncSetAttribute(fa_hmma_kernel,
                         cudaFuncAttributeMaxDynamicSharedMemorySize, FA_SMEM);

    // Conversions
    const int n4x = Mtot * Dm / 4;
    const int n4w = Dm * Dm / 4;
    cvt_x_kernel<<<(n4x + 255) / 256, 256>>>(x, xf, n4x);
    cvt_w_kernel<<<dim3((n4w + 255) / 256, 4), 256>>>(
        Ws[0], Ws[1], Ws[2], Ws[3], wh, wl);

    const size_t WSZ = (size_t)Dm * Dm;

    // Fused Q/K/V projections (fp16x2); Q hi/lo (scale folded), K single,
    // V hi/lo.
    const dim3 gqkv(Dm / 128, Mtot / 128, 3);
    hmma_gemm_kernel<true><<<gqkv, 256, GEMM_SMEM>>>(
        xf,
        wh + 0 * WSZ, wh + 1 * WSZ, wh + 2 * WSZ,
        wl + 0 * WSZ, wl + 1 * WSZ, wl + 2 * WSZ,
        bs[0], bs[1], bs[2],
        nullptr,
        qh, kf, vh,
        ql, nullptr, vl);

    // Attention (fp16x2, 64-query tiles, 4 CTAs/SM, longest-first)
    const dim3 ga(Sq / 64, Hh, Bc);
    fa_hmma_kernel<<<ga, 128, FA_SMEM>>>(qh, ql, kf, vh, vl, am, cf);

    // Output projection (fp16x2)
    const dim3 gg(Dm / 128, Mtot / 128, 1);
    hmma_gemm_kernel<false><<<gg, 256, GEMM_SMEM>>>(
        cf,
        wh + 3 * WSZ, wh + 3 * WSZ, wh + 3 * WSZ,
        wl + 3 * WSZ, wl + 3 * WSZ, wl + 3 * WSZ,
        bs[3], bs[3], bs[3],
        (float*)d_out,
        nullptr, nullptr, nullptr,
        nullptr, nullptr, nullptr);
}

// round 11
// speedup vs baseline: 1.7040x; 1.1099x over previous
#include <cuda_runtime.h>
#include <cuda_fp16.h>
#include <math.h>
#include <stdint.h>

// Problem constants
constexpr int Bc  = 4;
constexpr int Sq  = 2048;
constexpr int Dm  = 1024;
constexpr int Hh  = 16;
constexpr int HDd = 64;
constexpr int Mtot = Bc * Sq;           // 8192

// Scratch (device globals: allocation-free per harness rules)
__device__ __half g_xf[(size_t)Mtot * Dm];            // x fp16
__device__ __half g_wh[(size_t)4 * Dm * Dm];          // W hi fp16
__device__ __half g_wl[(size_t)4 * Dm * Dm];          // W lo fp16
__device__ __half g_cf[(size_t)Mtot * Dm];            // ctx fp16
__device__ __half g_qh[(size_t)Mtot * Dm];            // Q hi fp16
__device__ __half g_ql[(size_t)Mtot * Dm];            // Q lo fp16
__device__ __half g_kf[(size_t)Mtot * Dm];            // K single fp16
__device__ __half g_vf[(size_t)Mtot * Dm];            // V single fp16

// ---------------------------------------------------------------------------
// PTX helpers
// ---------------------------------------------------------------------------
__device__ __forceinline__ uint32_t smem_u32(const void* p) {
    uint32_t a;
    asm("{ .reg .u64 t; cvta.to.shared.u64 t, %1; cvt.u32.u64 %0, t; }" : "=r"(a) : "l"(p));
    return a;
}
__device__ __forceinline__ void ldm_x4(uint32_t (&r)[4], uint32_t saddr) {
    asm volatile("ldmatrix.sync.aligned.m8n8.x4.shared.b16 {%0,%1,%2,%3}, [%4];"
        : "=r"(r[0]), "=r"(r[1]), "=r"(r[2]), "=r"(r[3]) : "r"(saddr));
}
__device__ __forceinline__ void ldm_x4_t(uint32_t (&r)[4], uint32_t saddr) {
    asm volatile("ldmatrix.sync.aligned.m8n8.x4.trans.shared.b16 {%0,%1,%2,%3}, [%4];"
        : "=r"(r[0]), "=r"(r[1]), "=r"(r[2]), "=r"(r[3]) : "r"(saddr));
}
__device__ __forceinline__ void mma_fp16(float (&c)[4], const uint32_t (&a)[4],
                                         uint32_t b0, uint32_t b1) {
    asm volatile("mma.sync.aligned.m16n8k16.row.col.f32.f16.f16.f32 "
        "{%0,%1,%2,%3}, {%4,%5,%6,%7}, {%8,%9}, {%0,%1,%2,%3};"
        : "+f"(c[0]), "+f"(c[1]), "+f"(c[2]), "+f"(c[3])
        : "r"(a[0]), "r"(a[1]), "r"(a[2]), "r"(a[3]), "r"(b0), "r"(b1));
}
__device__ __forceinline__ void cp16(uint32_t dst, const void* src) {
    asm volatile("cp.async.cg.shared.global [%0], [%1], 16;" :: "r"(dst), "l"(src) : "memory");
}
#define CP_COMMIT() asm volatile("cp.async.commit_group;" ::: "memory")
#define CP_WAIT(n)  asm volatile("cp.async.wait_group %0;" :: "n"(n) : "memory")

__device__ __forceinline__ uint32_t hf2(float a, float b) {
    __half2 t = __floats2half2_rn(a, b);
    return *reinterpret_cast<uint32_t*>(&t);
}
__device__ __forceinline__ float hf16rt(float a) {
    return __half2float(__float2half_rn(a));
}
__device__ __forceinline__ uint32_t swz(int row, int chunk) {
    return (uint32_t)(row * 128 + ((chunk ^ (row & 7)) * 16));
}

// ---------------------------------------------------------------------------
// Conversions: x -> fp16; weights -> fp16 hi/lo (y-indexed over 4 weights)
// ---------------------------------------------------------------------------
__global__ __launch_bounds__(256) void cvt_x_kernel(const float* __restrict__ in,
                                                    __half* __restrict__ out, int n4)
{
    const int i = blockIdx.x * blockDim.x + threadIdx.x;
    if (i >= n4) return;
    const float4 v = ((const float4*)in)[i];
    uint2 u;
    u.x = hf2(v.x, v.y);
    u.y = hf2(v.z, v.w);
    ((uint2*)out)[i] = u;
}

__global__ __launch_bounds__(256) void cvt_w_kernel(
    const float* __restrict__ w0, const float* __restrict__ w1,
    const float* __restrict__ w2, const float* __restrict__ w3,
    __half* __restrict__ hi, __half* __restrict__ lo)
{
    const int n4 = Dm * Dm / 4;
    const int i = blockIdx.x * blockDim.x + threadIdx.x;
    if (i >= n4) return;
    const int wsel = blockIdx.y;
    const float* in = wsel == 0 ? w0 : wsel == 1 ? w1 : wsel == 2 ? w2 : w3;
    const size_t off = (size_t)wsel * n4 + i;
    const float4 v = ((const float4*)in)[i];
    union { __half h[4]; uint2 u; } H, L;
    const float vv[4] = {v.x, v.y, v.z, v.w};
#pragma unroll
    for (int j = 0; j < 4; j++) {
        H.h[j] = __float2half_rn(vv[j]);
        L.h[j] = __float2half_rn(vv[j] - __half2float(H.h[j]));
    }
    ((uint2*)hi)[off] = H.u;
    ((uint2*)lo)[off] = L.u;
}

// ---------------------------------------------------------------------------
// HMMA fp16 GEMM: out[M,N] = A_fp16[M,K] @ W[N,K]^T + bias
// W = Wh (+ Wl if Bl != null; 2-pass fp16x2, else single-pass plain fp16).
// 128x128 CTA tile, BK=64, 8 warps (2x4), cp.async 2-stage (96KB).
// SPLIT=true: writes [B,H,S,HD]; outL==null -> single fp16, else hi/lo.
// SPLIT=false: f32 [M,N].
// ---------------------------------------------------------------------------
constexpr int BKg = 64;
constexpr int NKC = Dm / BKg;                  // 16
constexpr int ATILE = 128 * 128;               // 16 KB
constexpr int STAGE_BYTES = 3 * ATILE;         // 48 KB
constexpr int GEMM_SMEM = 2 * STAGE_BYTES;     // 96 KB

template <bool SPLIT>
__global__ __launch_bounds__(256, 2) void hmma_gemm_kernel(
    const __half* __restrict__ Af,
    const __half* __restrict__ Bh0, const __half* __restrict__ Bh1,
    const __half* __restrict__ Bh2,
    const __half* __restrict__ Bl0, const __half* __restrict__ Bl1,
    const __half* __restrict__ Bl2,
    const float* __restrict__ bias0, const float* __restrict__ bias1,
    const float* __restrict__ bias2,
    float* __restrict__ outF,
    __half* __restrict__ oh0, __half* __restrict__ oh1,
    __half* __restrict__ oh2,
    __half* __restrict__ ol0, __half* __restrict__ ol1,
    __half* __restrict__ ol2)
{
    extern __shared__ char sm[];
    const uint32_t smb = smem_u32(sm);
    const int z    = blockIdx.z;
    const __half* Bh = z == 0 ? Bh0 : z == 1 ? Bh1 : Bh2;
    const __half* Bl = z == 0 ? Bl0 : z == 1 ? Bl1 : Bl2;
    const float* bias = z == 0 ? bias0 : z == 1 ? bias1 : bias2;
    __half* outH      = z == 0 ? oh0 : z == 1 ? oh1 : oh2;
    __half* outL      = z == 0 ? ol0 : z == 1 ? ol1 : ol2;
    const float scale = (SPLIT && z == 0) ? 0.125f : 1.0f;
    const bool hasLo  = (Bl != nullptr);

    const int t    = threadIdx.x;
    const int wid  = t >> 5;
    const int lane = t & 31;
    const int m0   = blockIdx.y * 128;
    const int n0   = blockIdx.x * 128;
    const int wm   = (wid & 1) * 64;
    const int wn   = (wid >> 1) * 32;

    auto load_stage = [&](int s, int kc) {
        const uint32_t ab  = smb + s * STAGE_BYTES;
        const uint32_t bhb = ab + ATILE;
        const uint32_t blb = ab + 2 * ATILE;
#pragma unroll
        for (int i = 0; i < 4; i++) {
            const int idx = t + i * 256;
            const int row = idx >> 3;
            const int c   = idx & 7;
            const int kofs = kc * BKg + c * 8;
            cp16(ab  + swz(row, c), Af + (size_t)(m0 + row) * Dm + kofs);
            cp16(bhb + swz(row, c), Bh + (size_t)(n0 + row) * Dm + kofs);
            if (hasLo)
                cp16(blb + swz(row, c), Bl + (size_t)(n0 + row) * Dm + kofs);
        }
        CP_COMMIT();
    };

    float acc[4][4][4];
#pragma unroll
    for (int i = 0; i < 4; i++)
#pragma unroll
        for (int j = 0; j < 4; j++)
#pragma unroll
            for (int r = 0; r < 4; r++) acc[i][j][r] = 0.0f;

    load_stage(0, 0);

    const int lrow = lane & 15;
    const int lsel = lane >> 4;

    int s = 0;
    for (int kc = 0; kc < NKC; kc++) {
        CP_WAIT(0);
        __syncthreads();
        if (kc + 1 < NKC) load_stage(s ^ 1, kc + 1);

        const uint32_t ab  = smb + s * STAGE_BYTES;
        const uint32_t bhb = ab + ATILE;
        const uint32_t blb = ab + 2 * ATILE;

#pragma unroll
        for (int k16 = 0; k16 < 4; k16++) {
            const int ch = k16 * 2 + lsel;
            uint32_t a_f[4][4];
#pragma unroll
            for (int mt = 0; mt < 4; mt++)
                ldm_x4(a_f[mt], ab + swz(wm + mt * 16 + lrow, ch));
            uint32_t b_h[2][4], b_l[2][4];
#pragma unroll
            for (int nt = 0; nt < 2; nt++) {
                const int row = wn + nt * 16 + lrow;
                ldm_x4(b_h[nt], bhb + swz(row, ch));
                if (hasLo) ldm_x4(b_l[nt], blb + swz(row, ch));
            }
#pragma unroll
            for (int mt = 0; mt < 4; mt++) {
#pragma unroll
                for (int n8 = 0; n8 < 4; n8++) {
                    const int nt = n8 >> 1, sl = n8 & 1;
                    mma_fp16(acc[mt][n8], a_f[mt], b_h[nt][sl], b_h[nt][sl + 2]);
                    if (hasLo)
                        mma_fp16(acc[mt][n8], a_f[mt], b_l[nt][sl], b_l[nt][sl + 2]);
                }
            }
        }
        s ^= 1;
    }

#pragma unroll
    for (int mt = 0; mt < 4; mt++) {
#pragma unroll
        for (int n8 = 0; n8 < 4; n8++) {
            const int r0 = m0 + wm + mt * 16 + (lane >> 2);
            const int c0 = n0 + wn + n8 * 8 + (lane & 3) * 2;
#pragma unroll
            for (int half = 0; half < 2; half++) {
                const int m = r0 + half * 8;
                const int b_ = m / Sq;
                const int s_ = m % Sq;
                const float v0 = (acc[mt][n8][half * 2 + 0] + bias[c0]) * scale;
                const float v1 = (acc[mt][n8][half * 2 + 1] + bias[c0 + 1]) * scale;
                if (SPLIT) {
                    const int h_ = c0 >> 6;
                    const int d_ = c0 & 63;
                    const size_t off =
                        ((((size_t)(b_ * Hh + h_)) * Sq + s_) * HDd + d_) >> 1;
                    ((uint32_t*)outH)[off] = hf2(v0, v1);
                    if (outL)
                        ((uint32_t*)outL)[off] =
                            hf2(v0 - hf16rt(v0), v1 - hf16rt(v1));
                } else {
                    float* dst = outF + (size_t)m * Dm + c0;
                    dst[0] = v0; dst[1] = v1;
                }
            }
        }
    }
}

// ---------------------------------------------------------------------------
// HMMA fp16 flash attention: CTA = (64 queries, head, batch), 4 warps.
// Q fp16 hi/lo (16KB, loaded once), K single fp16 double-buffered (2x8KB),
// V single fp16 single-buffered (8KB), mask 512B -> 40.5KB/CTA, 4 CTAs/SM.
// QK^T: 2 passes (Qh*K + Ql*K). PV: 1 pass (P*V), both P and V single fp16.
// Longest-first: qt = gridDim.x - 1 - blockIdx.x.
// ---------------------------------------------------------------------------
constexpr int FA_Q    = 16384;                 // Qh 8K + Ql 8K
constexpr int FA_KST  = 8192;                  // one K stage (single fp16)
constexpr int FA_VOFF = FA_Q + 2 * FA_KST;     // 32768
constexpr int FA_MOFF = FA_VOFF + 8192;        // 40960
constexpr int FA_SMEM = FA_MOFF + 512;         // 41472

__global__ __launch_bounds__(128, 4) void fa_hmma_kernel(
    const __half* __restrict__ Qh, const __half* __restrict__ Ql,
    const __half* __restrict__ Kf,
    const __half* __restrict__ Vf,
    const int* __restrict__ maskg,
    __half* __restrict__ Cf)
{
    extern __shared__ char sm[];
    const uint32_t smb = smem_u32(sm);
    const int t    = threadIdx.x;
    const int w    = t >> 5;
    const int lane = t & 31;
    const int qt   = gridDim.x - 1 - blockIdx.x;   // longest-first
    const int h    = blockIdx.y;
    const int b    = blockIdx.z;
    const size_t hb = ((size_t)(b * Hh + h)) * Sq * HDd;

    const uint32_t qhb = smb;
    const uint32_t qlb = smb + 8192;
    const uint32_t vfb = smb + FA_VOFF;

    auto load_k = [&](int s, int kt2) {
        const uint32_t kb = smb + FA_Q + s * FA_KST;
        const char* sK = (const char*)(Kf + hb + (size_t)kt2 * 64 * HDd);
#pragma unroll
        for (int i = 0; i < 4; i++) {
            const int idx = t + i * 128;
            const int row = idx >> 3, c = idx & 7;
            cp16(kb + swz(row, c), sK + idx * 16);
        }
        if (t < 16) cp16(smb + FA_MOFF + s * 256 + t * 16,
                         maskg + b * Sq + kt2 * 64 + t * 4);
        CP_COMMIT();
    };
    auto load_v = [&](int kt2) {
        const char* sV = (const char*)(Vf + hb + (size_t)kt2 * 64 * HDd);
#pragma unroll
        for (int i = 0; i < 4; i++) {
            const int idx = t + i * 128;
            const int row = idx >> 3, c = idx & 7;
            cp16(vfb + swz(row, c), sV + idx * 16);
        }
        CP_COMMIT();
    };

    // Prologue: Q tile hi/lo + K(0) + mask(0) in one group.
    {
        const char* srcH = (const char*)(Qh + hb + (size_t)qt * 64 * HDd);
        const char* srcL = (const char*)(Ql + hb + (size_t)qt * 64 * HDd);
#pragma unroll
        for (int i = 0; i < 4; i++) {
            const int idx = t + i * 128;
            const int row = idx >> 3, c = idx & 7;
            cp16(qhb + swz(row, c), srcH + idx * 16);
            cp16(qlb + swz(row, c), srcL + idx * 16);
        }
    }
    load_k(0, 0);

    const int lrow  = lane & 15;
    const int lsel  = lane >> 4;
    const int rl    = lane >> 2;
    const int cbase = (lane & 3) * 2;
    const int wr0   = w * 16;

    float m_i[2] = {-INFINITY, -INFINITY};
    float l_i[2] = {0.0f, 0.0f};
    float o[8][4];
#pragma unroll
    for (int n8 = 0; n8 < 8; n8++)
#pragma unroll
        for (int c = 0; c < 4; c++) o[n8][c] = 0.0f;

    for (int kt2 = 0; kt2 <= qt; kt2++) {
        const int s = kt2 & 1;

        __syncthreads();            // V buffer free (PV of prev tile done)
        load_v(kt2);                // completes under S/softmax below
        if (kt2 < qt) { load_k(s ^ 1, kt2 + 1); CP_WAIT(2); }
        else          { CP_WAIT(1); }
        __syncthreads();            // K(kt2)+mask visible

        const uint32_t kfb = smb + FA_Q + s * FA_KST;
        const int* msk = (const int*)(sm + FA_MOFF + s * 256);

        // ---- S = Q @ K^T (fp16x2: Qh*K + Ql*K) ----
        float sc[8][4];
#pragma unroll
        for (int n8 = 0; n8 < 8; n8++)
#pragma unroll
            for (int c = 0; c < 4; c++) sc[n8][c] = 0.0f;

#pragma unroll
        for (int k16 = 0; k16 < 4; k16++) {
            const int ch = k16 * 2 + lsel;
            uint32_t qf_h[4], qf_l[4];
            ldm_x4(qf_h, qhb + swz(wr0 + lrow, ch));
            ldm_x4(qf_l, qlb + swz(wr0 + lrow, ch));
            uint32_t kf[4][4];
#pragma unroll
            for (int nt = 0; nt < 4; nt++)
                ldm_x4(kf[nt], kfb + swz(nt * 16 + lrow, ch));
#pragma unroll
            for (int n8 = 0; n8 < 8; n8++) {
                const int nt = n8 >> 1, sl = n8 & 1;
                mma_fp16(sc[n8], qf_h, kf[nt][sl], kf[nt][sl + 2]);
                mma_fp16(sc[n8], qf_l, kf[nt][sl], kf[nt][sl + 2]);
            }
        }

        // ---- masking (pad overrides causal, reference order) ----
        const bool diag = (kt2 == qt);
        const int qi0 = qt * 64 + wr0 + rl;
#pragma unroll
        for (int n8 = 0; n8 < 8; n8++) {
#pragma unroll
            for (int c = 0; c < 4; c++) {
                const int colL = n8 * 8 + cbase + (c & 1);
                const int mv = msk[colL];
                if (mv == 0) sc[n8][c] = -1e9f;
                else if (diag) {
                    const int kj = kt2 * 64 + colL;
                    const int qi = qi0 + (c >> 1) * 8;
                    if (kj > qi) sc[n8][c] = -INFINITY;
                }
            }
        }

        // ---- online softmax (rows rl, rl+8) ----
#pragma unroll
        for (int r = 0; r < 2; r++) {
            float mx = -INFINITY;
#pragma unroll
            for (int n8 = 0; n8 < 8; n8++)
                mx = fmaxf(mx, fmaxf(sc[n8][2 * r], sc[n8][2 * r + 1]));
            mx = fmaxf(mx, __shfl_xor_sync(0xffffffffu, mx, 1));
            mx = fmaxf(mx, __shfl_xor_sync(0xffffffffu, mx, 2));
            const float mnew  = fmaxf(m_i[r], mx);
            const float alpha = __expf(m_i[r] - mnew);
            float sum = 0.0f;
#pragma unroll
            for (int n8 = 0; n8 < 8; n8++) {
                const float p0 = __expf(sc[n8][2 * r]     - mnew);
                const float p1 = __expf(sc[n8][2 * r + 1] - mnew);
                sc[n8][2 * r] = p0; sc[n8][2 * r + 1] = p1;
                sum += p0 + p1;
            }
            sum += __shfl_xor_sync(0xffffffffu, sum, 1);
            sum += __shfl_xor_sync(0xffffffffu, sum, 2);
            l_i[r] = l_i[r] * alpha + sum;
            m_i[r] = mnew;
#pragma unroll
            for (int n8 = 0; n8 < 8; n8++) {
                o[n8][2 * r] *= alpha; o[n8][2 * r + 1] *= alpha;
            }
        }

        // ---- P -> single fp16 A-fragments ----
        uint32_t pa[4][4];
#pragma unroll
        for (int j = 0; j < 4; j++) {
#pragma unroll
            for (int u = 0; u < 4; u++) {
                const int tile = 2 * j + (u >> 1);
                const int ci   = (u & 1) * 2;
                pa[j][u] = hf2(sc[tile][ci], sc[tile][ci + 1]);
            }
        }

        // ---- wait V(kt2), then O += P @ V (single pass) ----
        if (kt2 < qt) { CP_WAIT(1); } else { CP_WAIT(0); }
        __syncthreads();            // V visible

#pragma unroll
        for (int j = 0; j < 4; j++) {
            const int mrow = 16 * j + ((lane >> 3) & 1) * 8 + (lane & 7);
            uint32_t vf[4][4];
#pragma unroll
            for (int hp = 0; hp < 4; hp++) {
                const int chv = hp * 2 + (lane >> 4);
                ldm_x4_t(vf[hp], vfb + swz(mrow, chv));
            }
#pragma unroll
            for (int n8 = 0; n8 < 8; n8++) {
                const int hp = n8 >> 1, q_ = n8 & 1;
                mma_fp16(o[n8], pa[j], vf[hp][2 * q_], vf[hp][2 * q_ + 1]);
            }
        }
    }

    // ---- normalize + write ctx fp16 [B,S,D] ----
#pragma unroll
    for (int r = 0; r < 2; r++) {
        const float inv = 1.0f / l_i[r];
        const int m = qt * 64 + wr0 + rl + r * 8;
        const size_t rowoff = ((size_t)b * Sq + m) * Dm + h * HDd;
#pragma unroll
        for (int n8 = 0; n8 < 8; n8++) {
            const int col = n8 * 8 + cbase;
            *((uint32_t*)(Cf + rowoff + col)) =
                hf2(o[n8][2 * r] * inv, o[n8][2 * r + 1] * inv);
        }
    }
}

// ---------------------------------------------------------------------------
// Launch
// ---------------------------------------------------------------------------
extern "C" void kernel_launch(void* const* d_in, const int* in_sizes, int n_in,
                              void* d_out, int out_size)
{
    const float* x  = nullptr;
    const int*   am = nullptr;
    const float* Ws[4] = {nullptr, nullptr, nullptr, nullptr};
    const float* bs[4] = {nullptr, nullptr, nullptr, nullptr};
    int wi = 0, bi = 0;
    for (int i = 0; i < n_in; i++) {
        const long sz = in_sizes[i];
        if (sz == (long)Mtot * Dm)      x = (const float*)d_in[i];
        else if (sz == (long)Mtot)      am = (const int*)d_in[i];
        else if (sz == (long)Dm * Dm) { if (wi < 4) Ws[wi++] = (const float*)d_in[i]; }
        else if (sz == (long)Dm)      { if (bi < 4) bs[bi++] = (const float*)d_in[i]; }
    }

    __half *xf, *wh, *wl, *cf, *qh, *ql, *kf, *vf;
    cudaGetSymbolAddress((void**)&xf, g_xf);
    cudaGetSymbolAddress((void**)&wh, g_wh);
    cudaGetSymbolAddress((void**)&wl, g_wl);
    cudaGetSymbolAddress((void**)&cf, g_cf);
    cudaGetSymbolAddress((void**)&qh, g_qh);
    cudaGetSymbolAddress((void**)&ql, g_ql);
    cudaGetSymbolAddress((void**)&kf, g_kf);
    cudaGetSymbolAddress((void**)&vf, g_vf);

    cudaFuncSetAttribute(hmma_gemm_kernel<true>,
                         cudaFuncAttributeMaxDynamicSharedMemorySize, GEMM_SMEM);
    cudaFuncSetAttribute(hmma_gemm_kernel<false>,
                         cudaFuncAttributeMaxDynamicSharedMemorySize, GEMM_SMEM);
    cudaFuncSetAttribute(fa_hmma_kernel,
                         cudaFuncAttributeMaxDynamicSharedMemorySize, FA_SMEM);

    // Conversions
    const int n4x = Mtot * Dm / 4;
    const int n4w = Dm * Dm / 4;
    cvt_x_kernel<<<(n4x + 255) / 256, 256>>>(x, xf, n4x);
    cvt_w_kernel<<<dim3((n4w + 255) / 256, 4), 256>>>(
        Ws[0], Ws[1], Ws[2], Ws[3], wh, wl);

    const size_t WSZ = (size_t)Dm * Dm;

    // Fused Q/K/V projections:
    //  z=0 (Q): fp16x2 (W hi+lo), output hi/lo, scale folded.
    //  z=1 (K): fp16x2 (W hi+lo), output single fp16.
    //  z=2 (V): single-pass plain fp16 (Bl=null), output single fp16.
    const dim3 gqkv(Dm / 128, Mtot / 128, 3);
    hmma_gemm_kernel<true><<<gqkv, 256, GEMM_SMEM>>>(
        xf,
        wh + 0 * WSZ, wh + 1 * WSZ, wh + 2 * WSZ,
        wl + 0 * WSZ, wl + 1 * WSZ, nullptr,
        bs[0], bs[1], bs[2],
        nullptr,
        qh, kf, vf,
        ql, nullptr, nullptr);

    // Attention (QK fp16x2 on Q side; PV single pass)
    const dim3 ga(Sq / 64, Hh, Bc);
    fa_hmma_kernel<<<ga, 128, FA_SMEM>>>(qh, ql, kf, vf, am, cf);

    // Output projection: single-pass plain fp16 (Bl=null)
    const dim3 gg(Dm / 128, Mtot / 128, 1);
    hmma_gemm_kernel<false><<<gg, 256, GEMM_SMEM>>>(
        cf,
        wh + 3 * WSZ, wh + 3 * WSZ, wh + 3 * WSZ,
        nullptr, nullptr, nullptr,
        bs[3], bs[3], bs[3],
        (float*)d_out,
        nullptr, nullptr, nullptr,
        nullptr, nullptr, nullptr);
}

// round 12
// speedup vs baseline: 1.8854x; 1.1065x over previous
#include <cuda_runtime.h>
#include <cuda_fp16.h>
#include <math.h>
#include <stdint.h>

// Problem constants
constexpr int Bc  = 4;
constexpr int Sq  = 2048;
constexpr int Dm  = 1024;
constexpr int Hh  = 16;
constexpr int HDd = 64;
constexpr int Mtot = Bc * Sq;           // 8192

// Scratch (device globals: allocation-free per harness rules)
__device__ __half g_xf[(size_t)Mtot * Dm];            // x fp16
__device__ __half g_wh[(size_t)4 * Dm * Dm];          // W hi fp16
__device__ __half g_wl[(size_t)4 * Dm * Dm];          // W lo fp16
__device__ __half g_cf[(size_t)Mtot * Dm];            // ctx fp16
__device__ __half g_qf[(size_t)Mtot * Dm];            // Q single fp16
__device__ __half g_kf[(size_t)Mtot * Dm];            // K single fp16
__device__ __half g_vf[(size_t)Mtot * Dm];            // V single fp16

// ---------------------------------------------------------------------------
// PTX helpers
// ---------------------------------------------------------------------------
__device__ __forceinline__ uint32_t smem_u32(const void* p) {
    uint32_t a;
    asm("{ .reg .u64 t; cvta.to.shared.u64 t, %1; cvt.u32.u64 %0, t; }" : "=r"(a) : "l"(p));
    return a;
}
__device__ __forceinline__ void ldm_x4(uint32_t (&r)[4], uint32_t saddr) {
    asm volatile("ldmatrix.sync.aligned.m8n8.x4.shared.b16 {%0,%1,%2,%3}, [%4];"
        : "=r"(r[0]), "=r"(r[1]), "=r"(r[2]), "=r"(r[3]) : "r"(saddr));
}
__device__ __forceinline__ void ldm_x4_t(uint32_t (&r)[4], uint32_t saddr) {
    asm volatile("ldmatrix.sync.aligned.m8n8.x4.trans.shared.b16 {%0,%1,%2,%3}, [%4];"
        : "=r"(r[0]), "=r"(r[1]), "=r"(r[2]), "=r"(r[3]) : "r"(saddr));
}
__device__ __forceinline__ void mma_fp16(float (&c)[4], const uint32_t (&a)[4],
                                         uint32_t b0, uint32_t b1) {
    asm volatile("mma.sync.aligned.m16n8k16.row.col.f32.f16.f16.f32 "
        "{%0,%1,%2,%3}, {%4,%5,%6,%7}, {%8,%9}, {%0,%1,%2,%3};"
        : "+f"(c[0]), "+f"(c[1]), "+f"(c[2]), "+f"(c[3])
        : "r"(a[0]), "r"(a[1]), "r"(a[2]), "r"(a[3]), "r"(b0), "r"(b1));
}
__device__ __forceinline__ void cp16(uint32_t dst, const void* src) {
    asm volatile("cp.async.cg.shared.global [%0], [%1], 16;" :: "r"(dst), "l"(src) : "memory");
}
#define CP_COMMIT() asm volatile("cp.async.commit_group;" ::: "memory")
#define CP_WAIT(n)  asm volatile("cp.async.wait_group %0;" :: "n"(n) : "memory")

__device__ __forceinline__ uint32_t hf2(float a, float b) {
    __half2 t = __floats2half2_rn(a, b);
    return *reinterpret_cast<uint32_t*>(&t);
}
__device__ __forceinline__ float hf16rt(float a) {
    return __half2float(__float2half_rn(a));
}
__device__ __forceinline__ uint32_t swz(int row, int chunk) {
    return (uint32_t)(row * 128 + ((chunk ^ (row & 7)) * 16));
}

// ---------------------------------------------------------------------------
// Conversions: x -> fp16; weights -> fp16 hi/lo (y-indexed over 4 weights)
// ---------------------------------------------------------------------------
__global__ __launch_bounds__(256) void cvt_x_kernel(const float* __restrict__ in,
                                                    __half* __restrict__ out, int n4)
{
    const int i = blockIdx.x * blockDim.x + threadIdx.x;
    if (i >= n4) return;
    const float4 v = ((const float4*)in)[i];
    uint2 u;
    u.x = hf2(v.x, v.y);
    u.y = hf2(v.z, v.w);
    ((uint2*)out)[i] = u;
}

__global__ __launch_bounds__(256) void cvt_w_kernel(
    const float* __restrict__ w0, const float* __restrict__ w1,
    const float* __restrict__ w2, const float* __restrict__ w3,
    __half* __restrict__ hi, __half* __restrict__ lo)
{
    const int n4 = Dm * Dm / 4;
    const int i = blockIdx.x * blockDim.x + threadIdx.x;
    if (i >= n4) return;
    const int wsel = blockIdx.y;
    const float* in = wsel == 0 ? w0 : wsel == 1 ? w1 : wsel == 2 ? w2 : w3;
    const size_t off = (size_t)wsel * n4 + i;
    const float4 v = ((const float4*)in)[i];
    union { __half h[4]; uint2 u; } H, L;
    const float vv[4] = {v.x, v.y, v.z, v.w};
#pragma unroll
    for (int j = 0; j < 4; j++) {
        H.h[j] = __float2half_rn(vv[j]);
        L.h[j] = __float2half_rn(vv[j] - __half2float(H.h[j]));
    }
    ((uint2*)hi)[off] = H.u;
    ((uint2*)lo)[off] = L.u;
}

// ---------------------------------------------------------------------------
// HMMA fp16 GEMM: out[M,N] = A_fp16[M,K] @ W[N,K]^T + bias
// W = Wh (+ Wl if Bl != null; 2-pass fp16x2, else single-pass plain fp16).
// 128x128 CTA tile, BK=64, 8 warps (2x4), cp.async 2-stage (96KB).
// SPLIT=true: writes single fp16 in [B,H,S,HD]. SPLIT=false: f32 [M,N].
// ---------------------------------------------------------------------------
constexpr int BKg = 64;
constexpr int NKC = Dm / BKg;                  // 16
constexpr int ATILE = 128 * 128;               // 16 KB
constexpr int STAGE_BYTES = 3 * ATILE;         // 48 KB
constexpr int GEMM_SMEM = 2 * STAGE_BYTES;     // 96 KB

template <bool SPLIT>
__global__ __launch_bounds__(256, 2) void hmma_gemm_kernel(
    const __half* __restrict__ Af,
    const __half* __restrict__ Bh0, const __half* __restrict__ Bh1,
    const __half* __restrict__ Bh2,
    const __half* __restrict__ Bl0, const __half* __restrict__ Bl1,
    const __half* __restrict__ Bl2,
    const float* __restrict__ bias0, const float* __restrict__ bias1,
    const float* __restrict__ bias2,
    float* __restrict__ outF,
    __half* __restrict__ oh0, __half* __restrict__ oh1,
    __half* __restrict__ oh2)
{
    extern __shared__ char sm[];
    const uint32_t smb = smem_u32(sm);
    const int z    = blockIdx.z;
    const __half* Bh = z == 0 ? Bh0 : z == 1 ? Bh1 : Bh2;
    const __half* Bl = z == 0 ? Bl0 : z == 1 ? Bl1 : Bl2;
    const float* bias = z == 0 ? bias0 : z == 1 ? bias1 : bias2;
    __half* outH      = z == 0 ? oh0 : z == 1 ? oh1 : oh2;
    const float scale = (SPLIT && z == 0) ? 0.125f : 1.0f;
    const bool hasLo  = (Bl != nullptr);

    const int t    = threadIdx.x;
    const int wid  = t >> 5;
    const int lane = t & 31;
    const int m0   = blockIdx.y * 128;
    const int n0   = blockIdx.x * 128;
    const int wm   = (wid & 1) * 64;
    const int wn   = (wid >> 1) * 32;

    auto load_stage = [&](int s, int kc) {
        const uint32_t ab  = smb + s * STAGE_BYTES;
        const uint32_t bhb = ab + ATILE;
        const uint32_t blb = ab + 2 * ATILE;
#pragma unroll
        for (int i = 0; i < 4; i++) {
            const int idx = t + i * 256;
            const int row = idx >> 3;
            const int c   = idx & 7;
            const int kofs = kc * BKg + c * 8;
            cp16(ab  + swz(row, c), Af + (size_t)(m0 + row) * Dm + kofs);
            cp16(bhb + swz(row, c), Bh + (size_t)(n0 + row) * Dm + kofs);
            if (hasLo)
                cp16(blb + swz(row, c), Bl + (size_t)(n0 + row) * Dm + kofs);
        }
        CP_COMMIT();
    };

    float acc[4][4][4];
#pragma unroll
    for (int i = 0; i < 4; i++)
#pragma unroll
        for (int j = 0; j < 4; j++)
#pragma unroll
            for (int r = 0; r < 4; r++) acc[i][j][r] = 0.0f;

    load_stage(0, 0);

    const int lrow = lane & 15;
    const int lsel = lane >> 4;

    int s = 0;
    for (int kc = 0; kc < NKC; kc++) {
        CP_WAIT(0);
        __syncthreads();
        if (kc + 1 < NKC) load_stage(s ^ 1, kc + 1);

        const uint32_t ab  = smb + s * STAGE_BYTES;
        const uint32_t bhb = ab + ATILE;
        const uint32_t blb = ab + 2 * ATILE;

#pragma unroll
        for (int k16 = 0; k16 < 4; k16++) {
            const int ch = k16 * 2 + lsel;
            uint32_t a_f[4][4];
#pragma unroll
            for (int mt = 0; mt < 4; mt++)
                ldm_x4(a_f[mt], ab + swz(wm + mt * 16 + lrow, ch));
            uint32_t b_h[2][4], b_l[2][4];
#pragma unroll
            for (int nt = 0; nt < 2; nt++) {
                const int row = wn + nt * 16 + lrow;
                ldm_x4(b_h[nt], bhb + swz(row, ch));
                if (hasLo) ldm_x4(b_l[nt], blb + swz(row, ch));
            }
#pragma unroll
            for (int mt = 0; mt < 4; mt++) {
#pragma unroll
                for (int n8 = 0; n8 < 4; n8++) {
                    const int nt = n8 >> 1, sl = n8 & 1;
                    mma_fp16(acc[mt][n8], a_f[mt], b_h[nt][sl], b_h[nt][sl + 2]);
                    if (hasLo)
                        mma_fp16(acc[mt][n8], a_f[mt], b_l[nt][sl], b_l[nt][sl + 2]);
                }
            }
        }
        s ^= 1;
    }

#pragma unroll
    for (int mt = 0; mt < 4; mt++) {
#pragma unroll
        for (int n8 = 0; n8 < 4; n8++) {
            const int r0 = m0 + wm + mt * 16 + (lane >> 2);
            const int c0 = n0 + wn + n8 * 8 + (lane & 3) * 2;
#pragma unroll
            for (int half = 0; half < 2; half++) {
                const int m = r0 + half * 8;
                const int b_ = m / Sq;
                const int s_ = m % Sq;
                const float v0 = (acc[mt][n8][half * 2 + 0] + bias[c0]) * scale;
                const float v1 = (acc[mt][n8][half * 2 + 1] + bias[c0 + 1]) * scale;
                if (SPLIT) {
                    const int h_ = c0 >> 6;
                    const int d_ = c0 & 63;
                    const size_t off =
                        ((((size_t)(b_ * Hh + h_)) * Sq + s_) * HDd + d_) >> 1;
                    ((uint32_t*)outH)[off] = hf2(v0, v1);
                } else {
                    float* dst = outF + (size_t)m * Dm + c0;
                    dst[0] = v0; dst[1] = v1;
                }
            }
        }
    }
}

// ---------------------------------------------------------------------------
// HMMA fp16 flash attention: CTA = (64 queries, head, batch), 4 warps.
// Q single fp16 (8KB, once), K single fp16 double-buffered (2x8KB),
// V single fp16 single-buffered (8KB), mask 512B -> 32.5KB/CTA, 4 CTAs/SM.
// QK^T: 1 pass. PV: 1 pass. Pad mask via warp ballot (skipped if all-ones).
// Longest-first: qt = gridDim.x - 1 - blockIdx.x.
// ---------------------------------------------------------------------------
constexpr int FA_Q    = 8192;                  // Q single
constexpr int FA_KST  = 8192;                  // one K stage
constexpr int FA_VOFF = FA_Q + 2 * FA_KST;     // 24576
constexpr int FA_MOFF = FA_VOFF + 8192;        // 32768
constexpr int FA_SMEM = FA_MOFF + 512;         // 33280

__global__ __launch_bounds__(128, 4) void fa_hmma_kernel(
    const __half* __restrict__ Qf,
    const __half* __restrict__ Kf,
    const __half* __restrict__ Vf,
    const int* __restrict__ maskg,
    __half* __restrict__ Cf)
{
    extern __shared__ char sm[];
    const uint32_t smb = smem_u32(sm);
    const int t    = threadIdx.x;
    const int w    = t >> 5;
    const int lane = t & 31;
    const int qt   = gridDim.x - 1 - blockIdx.x;   // longest-first
    const int h    = blockIdx.y;
    const int b    = blockIdx.z;
    const size_t hb = ((size_t)(b * Hh + h)) * Sq * HDd;

    const uint32_t qfb = smb;
    const uint32_t vfb = smb + FA_VOFF;

    auto load_k = [&](int s, int kt2) {
        const uint32_t kb = smb + FA_Q + s * FA_KST;
        const char* sK = (const char*)(Kf + hb + (size_t)kt2 * 64 * HDd);
#pragma unroll
        for (int i = 0; i < 4; i++) {
            const int idx = t + i * 128;
            const int row = idx >> 3, c = idx & 7;
            cp16(kb + swz(row, c), sK + idx * 16);
        }
        if (t < 16) cp16(smb + FA_MOFF + s * 256 + t * 16,
                         maskg + b * Sq + kt2 * 64 + t * 4);
        CP_COMMIT();
    };
    auto load_v = [&](int kt2) {
        const char* sV = (const char*)(Vf + hb + (size_t)kt2 * 64 * HDd);
#pragma unroll
        for (int i = 0; i < 4; i++) {
            const int idx = t + i * 128;
            const int row = idx >> 3, c = idx & 7;
            cp16(vfb + swz(row, c), sV + idx * 16);
        }
        CP_COMMIT();
    };

    // Prologue: Q tile (single fp16) + K(0) + mask(0) in one group.
    {
        const char* srcQ = (const char*)(Qf + hb + (size_t)qt * 64 * HDd);
#pragma unroll
        for (int i = 0; i < 4; i++) {
            const int idx = t + i * 128;
            const int row = idx >> 3, c = idx & 7;
            cp16(qfb + swz(row, c), srcQ + idx * 16);
        }
    }
    load_k(0, 0);

    const int lrow  = lane & 15;
    const int lsel  = lane >> 4;
    const int rl    = lane >> 2;
    const int cbase = (lane & 3) * 2;
    const int wr0   = w * 16;

    float m_i[2] = {-INFINITY, -INFINITY};
    float l_i[2] = {0.0f, 0.0f};
    float o[8][4];
#pragma unroll
    for (int n8 = 0; n8 < 8; n8++)
#pragma unroll
        for (int c = 0; c < 4; c++) o[n8][c] = 0.0f;

    for (int kt2 = 0; kt2 <= qt; kt2++) {
        const int s = kt2 & 1;

        __syncthreads();            // V buffer free (PV of prev tile done)
        load_v(kt2);                // completes under S/softmax below
        if (kt2 < qt) { load_k(s ^ 1, kt2 + 1); CP_WAIT(2); }
        else          { CP_WAIT(1); }
        __syncthreads();            // K(kt2)+mask visible

        const uint32_t kfb = smb + FA_Q + s * FA_KST;
        const int* msk = (const int*)(sm + FA_MOFF + s * 256);

        // ---- S = Q @ K^T (single pass) ----
        float sc[8][4];
#pragma unroll
        for (int n8 = 0; n8 < 8; n8++)
#pragma unroll
            for (int c = 0; c < 4; c++) sc[n8][c] = 0.0f;

#pragma unroll
        for (int k16 = 0; k16 < 4; k16++) {
            const int ch = k16 * 2 + lsel;
            uint32_t qf[4];
            ldm_x4(qf, qfb + swz(wr0 + lrow, ch));
            uint32_t kf[4][4];
#pragma unroll
            for (int nt = 0; nt < 4; nt++)
                ldm_x4(kf[nt], kfb + swz(nt * 16 + lrow, ch));
#pragma unroll
            for (int n8 = 0; n8 < 8; n8++) {
                const int nt = n8 >> 1, sl = n8 & 1;
                mma_fp16(sc[n8], qf, kf[nt][sl], kf[nt][sl + 2]);
            }
        }

        // ---- masking: causal first, pad overrides (reference order) ----
        if (kt2 == qt) {
            const int qi0 = qt * 64 + wr0 + rl;
#pragma unroll
            for (int n8 = 0; n8 < 8; n8++) {
#pragma unroll
                for (int c = 0; c < 4; c++) {
                    const int kj = kt2 * 64 + n8 * 8 + cbase + (c & 1);
                    const int qi = qi0 + (c >> 1) * 8;
                    if (kj > qi) sc[n8][c] = -INFINITY;
                }
            }
        }
        // Pad mask as warp ballot bitmask (2 LDS + 2 ballots per tile).
        const uint32_t bm0 = __ballot_sync(0xffffffffu, msk[lane] != 0);
        const uint32_t bm1 = __ballot_sync(0xffffffffu, msk[lane + 32] != 0);
        if ((bm0 & bm1) != 0xffffffffu) {
#pragma unroll
            for (int n8 = 0; n8 < 8; n8++) {
#pragma unroll
                for (int c = 0; c < 4; c++) {
                    const int colL = n8 * 8 + cbase + (c & 1);
                    const uint32_t bit =
                        (colL < 32 ? bm0 >> colL : bm1 >> (colL - 32)) & 1u;
                    if (!bit) sc[n8][c] = -1e9f;
                }
            }
        }

        // ---- online softmax (rows rl, rl+8) ----
#pragma unroll
        for (int r = 0; r < 2; r++) {
            float mx = -INFINITY;
#pragma unroll
            for (int n8 = 0; n8 < 8; n8++)
                mx = fmaxf(mx, fmaxf(sc[n8][2 * r], sc[n8][2 * r + 1]));
            mx = fmaxf(mx, __shfl_xor_sync(0xffffffffu, mx, 1));
            mx = fmaxf(mx, __shfl_xor_sync(0xffffffffu, mx, 2));
            const float mnew  = fmaxf(m_i[r], mx);
            const float alpha = __expf(m_i[r] - mnew);
            float sum = 0.0f;
#pragma unroll
            for (int n8 = 0; n8 < 8; n8++) {
                const float p0 = __expf(sc[n8][2 * r]     - mnew);
                const float p1 = __expf(sc[n8][2 * r + 1] - mnew);
                sc[n8][2 * r] = p0; sc[n8][2 * r + 1] = p1;
                sum += p0 + p1;
            }
            sum += __shfl_xor_sync(0xffffffffu, sum, 1);
            sum += __shfl_xor_sync(0xffffffffu, sum, 2);
            l_i[r] = l_i[r] * alpha + sum;
            m_i[r] = mnew;
#pragma unroll
            for (int n8 = 0; n8 < 8; n8++) {
                o[n8][2 * r] *= alpha; o[n8][2 * r + 1] *= alpha;
            }
        }

        // ---- P -> single fp16 A-fragments ----
        uint32_t pa[4][4];
#pragma unroll
        for (int j = 0; j < 4; j++) {
#pragma unroll
            for (int u = 0; u < 4; u++) {
                const int tile = 2 * j + (u >> 1);
                const int ci   = (u & 1) * 2;
                pa[j][u] = hf2(sc[tile][ci], sc[tile][ci + 1]);
            }
        }

        // ---- wait V(kt2), then O += P @ V (single pass) ----
        if (kt2 < qt) { CP_WAIT(1); } else { CP_WAIT(0); }
        __syncthreads();            // V visible

#pragma unroll
        for (int j = 0; j < 4; j++) {
            const int mrow = 16 * j + ((lane >> 3) & 1) * 8 + (lane & 7);
            uint32_t vf[4][4];
#pragma unroll
            for (int hp = 0; hp < 4; hp++) {
                const int chv = hp * 2 + (lane >> 4);
                ldm_x4_t(vf[hp], vfb + swz(mrow, chv));
            }
#pragma unroll
            for (int n8 = 0; n8 < 8; n8++) {
                const int hp = n8 >> 1, q_ = n8 & 1;
                mma_fp16(o[n8], pa[j], vf[hp][2 * q_], vf[hp][2 * q_ + 1]);
            }
        }
    }

    // ---- normalize + write ctx fp16 [B,S,D] ----
#pragma unroll
    for (int r = 0; r < 2; r++) {
        const float inv = 1.0f / l_i[r];
        const int m = qt * 64 + wr0 + rl + r * 8;
        const size_t rowoff = ((size_t)b * Sq + m) * Dm + h * HDd;
#pragma unroll
        for (int n8 = 0; n8 < 8; n8++) {
            const int col = n8 * 8 + cbase;
            *((uint32_t*)(Cf + rowoff + col)) =
                hf2(o[n8][2 * r] * inv, o[n8][2 * r + 1] * inv);
        }
    }
}

// ---------------------------------------------------------------------------
// Launch
// ---------------------------------------------------------------------------
extern "C" void kernel_launch(void* const* d_in, const int* in_sizes, int n_in,
                              void* d_out, int out_size)
{
    const float* x  = nullptr;
    const int*   am = nullptr;
    const float* Ws[4] = {nullptr, nullptr, nullptr, nullptr};
    const float* bs[4] = {nullptr, nullptr, nullptr, nullptr};
    int wi = 0, bi = 0;
    for (int i = 0; i < n_in; i++) {
        const long sz = in_sizes[i];
        if (sz == (long)Mtot * Dm)      x = (const float*)d_in[i];
        else if (sz == (long)Mtot)      am = (const int*)d_in[i];
        else if (sz == (long)Dm * Dm) { if (wi < 4) Ws[wi++] = (const float*)d_in[i]; }
        else if (sz == (long)Dm)      { if (bi < 4) bs[bi++] = (const float*)d_in[i]; }
    }

    __half *xf, *wh, *wl, *cf, *qf, *kf, *vf;
    cudaGetSymbolAddress((void**)&xf, g_xf);
    cudaGetSymbolAddress((void**)&wh, g_wh);
    cudaGetSymbolAddress((void**)&wl, g_wl);
    cudaGetSymbolAddress((void**)&cf, g_cf);
    cudaGetSymbolAddress((void**)&qf, g_qf);
    cudaGetSymbolAddress((void**)&kf, g_kf);
    cudaGetSymbolAddress((void**)&vf, g_vf);

    cudaFuncSetAttribute(hmma_gemm_kernel<true>,
                         cudaFuncAttributeMaxDynamicSharedMemorySize, GEMM_SMEM);
    cudaFuncSetAttribute(hmma_gemm_kernel<false>,
                         cudaFuncAttributeMaxDynamicSharedMemorySize, GEMM_SMEM);
    cudaFuncSetAttribute(fa_hmma_kernel,
                         cudaFuncAttributeMaxDynamicSharedMemorySize, FA_SMEM);

    // Conversions
    const int n4x = Mtot * Dm / 4;
    const int n4w = Dm * Dm / 4;
    cvt_x_kernel<<<(n4x + 255) / 256, 256>>>(x, xf, n4x);
    cvt_w_kernel<<<dim3((n4w + 255) / 256, 4), 256>>>(
        Ws[0], Ws[1], Ws[2], Ws[3], wh, wl);

    const size_t WSZ = (size_t)Dm * Dm;

    // Fused Q/K/V projections:
    //  z=0 (Q): fp16x2 (W hi+lo), single fp16 out, scale folded.
    //  z=1 (K): fp16x2 (W hi+lo), single fp16 out.
    //  z=2 (V): single-pass plain fp16 (Bl=null), single fp16 out.
    const dim3 gqkv(Dm / 128, Mtot / 128, 3);
    hmma_gemm_kernel<true><<<gqkv, 256, GEMM_SMEM>>>(
        xf,
        wh + 0 * WSZ, wh + 1 * WSZ, wh + 2 * WSZ,
        wl + 0 * WSZ, wl + 1 * WSZ, nullptr,
        bs[0], bs[1], bs[2],
        nullptr,
        qf, kf, vf);

    // Attention (single-pass QK^T and PV)
    const dim3 ga(Sq / 64, Hh, Bc);
    fa_hmma_kernel<<<ga, 128, FA_SMEM>>>(qf, kf, vf, am, cf);

    // Output projection: single-pass plain fp16 (Bl=null)
    const dim3 gg(Dm / 128, Mtot / 128, 1);
    hmma_gemm_kernel<false><<<gg, 256, GEMM_SMEM>>>(
        cf,
        wh + 3 * WSZ, wh + 3 * WSZ, wh + 3 * WSZ,
        nullptr, nullptr, nullptr,
        bs[3], bs[3], bs[3],
        (float*)d_out,
        nullptr, nullptr, nullptr);
}

// round 13
// speedup vs baseline: 2.6651x; 1.4135x over previous
#include <cuda_runtime.h>
#include <cuda_fp16.h>
#include <math.h>
#include <stdint.h>

// Problem constants
constexpr int Bc  = 4;
constexpr int Sq  = 2048;
constexpr int Dm  = 1024;
constexpr int Hh  = 16;
constexpr int HDd = 64;
constexpr int Mtot = Bc * Sq;           // 8192

// Scratch (device globals: allocation-free per harness rules)
__device__ __half g_xf[(size_t)Mtot * Dm];            // x fp16
__device__ __half g_wf[(size_t)4 * Dm * Dm];          // W fp16 (hi only)
__device__ __half g_cf[(size_t)Mtot * Dm];            // ctx fp16
__device__ __half g_qf[(size_t)Mtot * Dm];            // Q fp16 (scale*log2e folded)
__device__ __half g_kf[(size_t)Mtot * Dm];            // K fp16
__device__ __half g_vf[(size_t)Mtot * Dm];            // V fp16

// ---------------------------------------------------------------------------
// PTX helpers
// ---------------------------------------------------------------------------
__device__ __forceinline__ uint32_t smem_u32(const void* p) {
    uint32_t a;
    asm("{ .reg .u64 t; cvta.to.shared.u64 t, %1; cvt.u32.u64 %0, t; }" : "=r"(a) : "l"(p));
    return a;
}
__device__ __forceinline__ void ldm_x4(uint32_t (&r)[4], uint32_t saddr) {
    asm volatile("ldmatrix.sync.aligned.m8n8.x4.shared.b16 {%0,%1,%2,%3}, [%4];"
        : "=r"(r[0]), "=r"(r[1]), "=r"(r[2]), "=r"(r[3]) : "r"(saddr));
}
__device__ __forceinline__ void ldm_x4_t(uint32_t (&r)[4], uint32_t saddr) {
    asm volatile("ldmatrix.sync.aligned.m8n8.x4.trans.shared.b16 {%0,%1,%2,%3}, [%4];"
        : "=r"(r[0]), "=r"(r[1]), "=r"(r[2]), "=r"(r[3]) : "r"(saddr));
}
__device__ __forceinline__ void mma_fp16(float (&c)[4], const uint32_t (&a)[4],
                                         uint32_t b0, uint32_t b1) {
    asm volatile("mma.sync.aligned.m16n8k16.row.col.f32.f16.f16.f32 "
        "{%0,%1,%2,%3}, {%4,%5,%6,%7}, {%8,%9}, {%0,%1,%2,%3};"
        : "+f"(c[0]), "+f"(c[1]), "+f"(c[2]), "+f"(c[3])
        : "r"(a[0]), "r"(a[1]), "r"(a[2]), "r"(a[3]), "r"(b0), "r"(b1));
}
__device__ __forceinline__ void cp16(uint32_t dst, const void* src) {
    asm volatile("cp.async.cg.shared.global [%0], [%1], 16;" :: "r"(dst), "l"(src) : "memory");
}
#define CP_COMMIT() asm volatile("cp.async.commit_group;" ::: "memory")
#define CP_WAIT(n)  asm volatile("cp.async.wait_group %0;" :: "n"(n) : "memory")

__device__ __forceinline__ uint32_t hf2(float a, float b) {
    __half2 t = __floats2half2_rn(a, b);
    return *reinterpret_cast<uint32_t*>(&t);
}
__device__ __forceinline__ uint32_t swz(int row, int chunk) {
    return (uint32_t)(row * 128 + ((chunk ^ (row & 7)) * 16));
}

// ---------------------------------------------------------------------------
// Conversions: x -> fp16; weights -> fp16 (y-indexed over 4 weights)
// ---------------------------------------------------------------------------
__global__ __launch_bounds__(256) void cvt_x_kernel(const float* __restrict__ in,
                                                    __half* __restrict__ out, int n4)
{
    const int i = blockIdx.x * blockDim.x + threadIdx.x;
    if (i >= n4) return;
    const float4 v = ((const float4*)in)[i];
    uint2 u;
    u.x = hf2(v.x, v.y);
    u.y = hf2(v.z, v.w);
    ((uint2*)out)[i] = u;
}

__global__ __launch_bounds__(256) void cvt_w_kernel(
    const float* __restrict__ w0, const float* __restrict__ w1,
    const float* __restrict__ w2, const float* __restrict__ w3,
    __half* __restrict__ outw)
{
    const int n4 = Dm * Dm / 4;
    const int i = blockIdx.x * blockDim.x + threadIdx.x;
    if (i >= n4) return;
    const int wsel = blockIdx.y;
    const float* in = wsel == 0 ? w0 : wsel == 1 ? w1 : wsel == 2 ? w2 : w3;
    const size_t off = (size_t)wsel * n4 + i;
    const float4 v = ((const float4*)in)[i];
    uint2 u;
    u.x = hf2(v.x, v.y);
    u.y = hf2(v.z, v.w);
    ((uint2*)outw)[off] = u;
}

// ---------------------------------------------------------------------------
// HMMA fp16 GEMM (single-pass): out[M,N] = A_fp16[M,K] @ W[N,K]^T + bias
// 128x128 CTA tile, BK=64, 8 warps (2x4), cp.async 3-stage ring (96KB).
// SPLIT=true: writes single fp16 in [B,H,S,HD], z selects W/bias/out.
// SPLIT=false: f32 [M,N].
// ---------------------------------------------------------------------------
constexpr int BKg = 64;
constexpr int NKC = Dm / BKg;                  // 16
constexpr int ATILE = 128 * 128;               // 16 KB
constexpr int STAGE_BYTES = 2 * ATILE;         // 32 KB (A + B)
constexpr int GEMM_SMEM = 3 * STAGE_BYTES;     // 96 KB

template <bool SPLIT>
__global__ __launch_bounds__(256, 2) void hmma_gemm_kernel(
    const __half* __restrict__ Af,
    const __half* __restrict__ B0, const __half* __restrict__ B1,
    const __half* __restrict__ B2,
    const float* __restrict__ bias0, const float* __restrict__ bias1,
    const float* __restrict__ bias2,
    float* __restrict__ outF,
    __half* __restrict__ oh0, __half* __restrict__ oh1,
    __half* __restrict__ oh2,
    float scale0)
{
    extern __shared__ char sm[];
    const uint32_t smb = smem_u32(sm);
    const int z    = blockIdx.z;
    const __half* Bw  = z == 0 ? B0 : z == 1 ? B1 : B2;
    const float* bias = z == 0 ? bias0 : z == 1 ? bias1 : bias2;
    __half* outH      = z == 0 ? oh0 : z == 1 ? oh1 : oh2;
    const float scale = (SPLIT && z == 0) ? scale0 : 1.0f;

    const int t    = threadIdx.x;
    const int wid  = t >> 5;
    const int lane = t & 31;
    const int m0   = blockIdx.y * 128;
    const int n0   = blockIdx.x * 128;
    const int wm   = (wid & 1) * 64;
    const int wn   = (wid >> 1) * 32;

    auto load_stage = [&](int s, int kc) {
        const uint32_t ab = smb + s * STAGE_BYTES;
        const uint32_t bb = ab + ATILE;
#pragma unroll
        for (int i = 0; i < 4; i++) {
            const int idx = t + i * 256;
            const int row = idx >> 3;
            const int c   = idx & 7;
            const int kofs = kc * BKg + c * 8;
            cp16(ab + swz(row, c), Af + (size_t)(m0 + row) * Dm + kofs);
            cp16(bb + swz(row, c), Bw + (size_t)(n0 + row) * Dm + kofs);
        }
        CP_COMMIT();
    };

    float acc[4][4][4];
#pragma unroll
    for (int i = 0; i < 4; i++)
#pragma unroll
        for (int j = 0; j < 4; j++)
#pragma unroll
            for (int r = 0; r < 4; r++) acc[i][j][r] = 0.0f;

    load_stage(0, 0);
    load_stage(1, 1);

    const int lrow = lane & 15;
    const int lsel = lane >> 4;

    int s = 0;
    for (int kc = 0; kc < NKC; kc++) {
        if (kc + 1 < NKC) { CP_WAIT(1); } else { CP_WAIT(0); }
        __syncthreads();
        if (kc + 2 < NKC) {
            int s2 = s + 2; if (s2 >= 3) s2 -= 3;
            load_stage(s2, kc + 2);
        }

        const uint32_t ab = smb + s * STAGE_BYTES;
        const uint32_t bb = ab + ATILE;

#pragma unroll
        for (int k16 = 0; k16 < 4; k16++) {
            const int ch = k16 * 2 + lsel;
            uint32_t a_f[4][4];
#pragma unroll
            for (int mt = 0; mt < 4; mt++)
                ldm_x4(a_f[mt], ab + swz(wm + mt * 16 + lrow, ch));
            uint32_t b_f[2][4];
#pragma unroll
            for (int nt = 0; nt < 2; nt++)
                ldm_x4(b_f[nt], bb + swz(wn + nt * 16 + lrow, ch));
#pragma unroll
            for (int mt = 0; mt < 4; mt++) {
#pragma unroll
                for (int n8 = 0; n8 < 4; n8++) {
                    const int nt = n8 >> 1, sl = n8 & 1;
                    mma_fp16(acc[mt][n8], a_f[mt], b_f[nt][sl], b_f[nt][sl + 2]);
                }
            }
        }
        if (++s == 3) s = 0;
    }

#pragma unroll
    for (int mt = 0; mt < 4; mt++) {
#pragma unroll
        for (int n8 = 0; n8 < 4; n8++) {
            const int r0 = m0 + wm + mt * 16 + (lane >> 2);
            const int c0 = n0 + wn + n8 * 8 + (lane & 3) * 2;
#pragma unroll
            for (int half = 0; half < 2; half++) {
                const int m = r0 + half * 8;
                const int b_ = m / Sq;
                const int s_ = m % Sq;
                const float v0 = (acc[mt][n8][half * 2 + 0] + bias[c0]) * scale;
                const float v1 = (acc[mt][n8][half * 2 + 1] + bias[c0 + 1]) * scale;
                if (SPLIT) {
                    const int h_ = c0 >> 6;
                    const int d_ = c0 & 63;
                    const size_t off =
                        ((((size_t)(b_ * Hh + h_)) * Sq + s_) * HDd + d_) >> 1;
                    ((uint32_t*)outH)[off] = hf2(v0, v1);
                } else {
                    float* dst = outF + (size_t)m * Dm + c0;
                    dst[0] = v0; dst[1] = v1;
                }
            }
        }
    }
}

// ---------------------------------------------------------------------------
// HMMA fp16 flash attention: CTA = (64 queries, head, batch), 4 warps.
// Q fp16 (8KB, scale*log2e folded), K+V fp16 double-buffered (2x16KB),
// mask 2x256B -> 41KB/CTA, 4 CTAs/SM. QK^T and PV single pass. Softmax in
// base-2 (exp2f). Pad mask via warp ballot (skipped when all-ones).
// Longest-first: qt = gridDim.x - 1 - blockIdx.x.
// ---------------------------------------------------------------------------
constexpr int FA_Q    = 8192;
constexpr int FA_KVST = 16384;                 // K 8KB + V 8KB
constexpr int FA_MOFF = FA_Q + 2 * FA_KVST;    // 40960
constexpr int FA_SMEM = FA_MOFF + 512;         // 41472

__global__ __launch_bounds__(128, 4) void fa_hmma_kernel(
    const __half* __restrict__ Qf,
    const __half* __restrict__ Kf,
    const __half* __restrict__ Vf,
    const int* __restrict__ maskg,
    __half* __restrict__ Cf)
{
    extern __shared__ char sm[];
    const uint32_t smb = smem_u32(sm);
    const int t    = threadIdx.x;
    const int w    = t >> 5;
    const int lane = t & 31;
    const int qt   = gridDim.x - 1 - blockIdx.x;   // longest-first
    const int h    = blockIdx.y;
    const int b    = blockIdx.z;
    const size_t hb = ((size_t)(b * Hh + h)) * Sq * HDd;

    const uint32_t qfb = smb;

    auto load_kv = [&](int s, int kt2) {
        const uint32_t kb = smb + FA_Q + s * FA_KVST;
        const char* sK = (const char*)(Kf + hb + (size_t)kt2 * 64 * HDd);
        const char* sV = (const char*)(Vf + hb + (size_t)kt2 * 64 * HDd);
#pragma unroll
        for (int i = 0; i < 4; i++) {
            const int idx = t + i * 128;
            const int row = idx >> 3, c = idx & 7;
            cp16(kb + swz(row, c), sK + idx * 16);
            cp16(kb + 8192 + swz(row, c), sV + idx * 16);
        }
        if (t < 16) cp16(smb + FA_MOFF + s * 256 + t * 16,
                         maskg + b * Sq + kt2 * 64 + t * 4);
        CP_COMMIT();
    };

    // Prologue: Q tile + K/V(0) + mask(0) in one group.
    {
        const char* srcQ = (const char*)(Qf + hb + (size_t)qt * 64 * HDd);
#pragma unroll
        for (int i = 0; i < 4; i++) {
            const int idx = t + i * 128;
            const int row = idx >> 3, c = idx & 7;
            cp16(qfb + swz(row, c), srcQ + idx * 16);
        }
    }
    load_kv(0, 0);

    const int lrow  = lane & 15;
    const int lsel  = lane >> 4;
    const int rl    = lane >> 2;
    const int cbase = (lane & 3) * 2;
    const int wr0   = w * 16;

    float m_i[2] = {-INFINITY, -INFINITY};
    float l_i[2] = {0.0f, 0.0f};
    float o[8][4];
#pragma unroll
    for (int n8 = 0; n8 < 8; n8++)
#pragma unroll
        for (int c = 0; c < 4; c++) o[n8][c] = 0.0f;

    for (int kt2 = 0; kt2 <= qt; kt2++) {
        const int s = kt2 & 1;

        __syncthreads();                 // stage s free (reads of prev use done)
        if (kt2 < qt) { load_kv(s ^ 1, kt2 + 1); CP_WAIT(1); }
        else          { CP_WAIT(0); }
        __syncthreads();                 // stage s visible

        const uint32_t kfb = smb + FA_Q + s * FA_KVST;
        const uint32_t vfb = kfb + 8192;
        const int* msk = (const int*)(sm + FA_MOFF + s * 256);

        // ---- S = Q @ K^T (single pass; scores pre-scaled by 0.125*log2e) ----
        float sc[8][4];
#pragma unroll
        for (int n8 = 0; n8 < 8; n8++)
#pragma unroll
            for (int c = 0; c < 4; c++) sc[n8][c] = 0.0f;

#pragma unroll
        for (int k16 = 0; k16 < 4; k16++) {
            const int ch = k16 * 2 + lsel;
            uint32_t qf[4];
            ldm_x4(qf, qfb + swz(wr0 + lrow, ch));
            uint32_t kf[4][4];
#pragma unroll
            for (int nt = 0; nt < 4; nt++)
                ldm_x4(kf[nt], kfb + swz(nt * 16 + lrow, ch));
#pragma unroll
            for (int n8 = 0; n8 < 8; n8++) {
                const int nt = n8 >> 1, sl = n8 & 1;
                mma_fp16(sc[n8], qf, kf[nt][sl], kf[nt][sl + 2]);
            }
        }

        // ---- masking: causal on diagonal; pad via ballot bitmask ----
        if (kt2 == qt) {
            const int qi0 = qt * 64 + wr0 + rl;
#pragma unroll
            for (int n8 = 0; n8 < 8; n8++) {
#pragma unroll
                for (int c = 0; c < 4; c++) {
                    const int kj = kt2 * 64 + n8 * 8 + cbase + (c & 1);
                    const int qi = qi0 + (c >> 1) * 8;
                    if (kj > qi) sc[n8][c] = -INFINITY;
                }
            }
        }
        const uint32_t bm0 = __ballot_sync(0xffffffffu, msk[lane] != 0);
        const uint32_t bm1 = __ballot_sync(0xffffffffu, msk[lane + 32] != 0);
        if ((bm0 & bm1) != 0xffffffffu) {
#pragma unroll
            for (int n8 = 0; n8 < 8; n8++) {
#pragma unroll
                for (int c = 0; c < 4; c++) {
                    const int colL = n8 * 8 + cbase + (c & 1);
                    const uint32_t bit =
                        (colL < 32 ? bm0 >> colL : bm1 >> (colL - 32)) & 1u;
                    if (!bit) sc[n8][c] = -1e9f;
                }
            }
        }

        // ---- online softmax in base-2 (rows rl, rl+8) ----
#pragma unroll
        for (int r = 0; r < 2; r++) {
            float mx = -INFINITY;
#pragma unroll
            for (int n8 = 0; n8 < 8; n8++)
                mx = fmaxf(mx, fmaxf(sc[n8][2 * r], sc[n8][2 * r + 1]));
            mx = fmaxf(mx, __shfl_xor_sync(0xffffffffu, mx, 1));
            mx = fmaxf(mx, __shfl_xor_sync(0xffffffffu, mx, 2));
            const float mnew  = fmaxf(m_i[r], mx);
            const float alpha = exp2f(m_i[r] - mnew);
            float sum = 0.0f;
#pragma unroll
            for (int n8 = 0; n8 < 8; n8++) {
                const float p0 = exp2f(sc[n8][2 * r]     - mnew);
                const float p1 = exp2f(sc[n8][2 * r + 1] - mnew);
                sc[n8][2 * r] = p0; sc[n8][2 * r + 1] = p1;
                sum += p0 + p1;
            }
            sum += __shfl_xor_sync(0xffffffffu, sum, 1);
            sum += __shfl_xor_sync(0xffffffffu, sum, 2);
            l_i[r] = l_i[r] * alpha + sum;
            m_i[r] = mnew;
#pragma unroll
            for (int n8 = 0; n8 < 8; n8++) {
                o[n8][2 * r] *= alpha; o[n8][2 * r + 1] *= alpha;
            }
        }

        // ---- P -> single fp16 A-fragments ----
        uint32_t pa[4][4];
#pragma unroll
        for (int j = 0; j < 4; j++) {
#pragma unroll
            for (int u = 0; u < 4; u++) {
                const int tile = 2 * j + (u >> 1);
                const int ci   = (u & 1) * 2;
                pa[j][u] = hf2(sc[tile][ci], sc[tile][ci + 1]);
            }
        }

        // ---- O += P @ V (single pass) ----
#pragma unroll
        for (int j = 0; j < 4; j++) {
            const int mrow = 16 * j + ((lane >> 3) & 1) * 8 + (lane & 7);
            uint32_t vf[4][4];
#pragma unroll
            for (int hp = 0; hp < 4; hp++) {
                const int chv = hp * 2 + (lane >> 4);
                ldm_x4_t(vf[hp], vfb + swz(mrow, chv));
            }
#pragma unroll
            for (int n8 = 0; n8 < 8; n8++) {
                const int hp = n8 >> 1, q_ = n8 & 1;
                mma_fp16(o[n8], pa[j], vf[hp][2 * q_], vf[hp][2 * q_ + 1]);
            }
        }
    }

    // ---- normalize + write ctx fp16 [B,S,D] ----
#pragma unroll
    for (int r = 0; r < 2; r++) {
        const float inv = 1.0f / l_i[r];
        const int m = qt * 64 + wr0 + rl + r * 8;
        const size_t rowoff = ((size_t)b * Sq + m) * Dm + h * HDd;
#pragma unroll
        for (int n8 = 0; n8 < 8; n8++) {
            const int col = n8 * 8 + cbase;
            *((uint32_t*)(Cf + rowoff + col)) =
                hf2(o[n8][2 * r] * inv, o[n8][2 * r + 1] * inv);
        }
    }
}

// ---------------------------------------------------------------------------
// Launch
// ---------------------------------------------------------------------------
extern "C" void kernel_launch(void* const* d_in, const int* in_sizes, int n_in,
                              void* d_out, int out_size)
{
    const float* x  = nullptr;
    const int*   am = nullptr;
    const float* Ws[4] = {nullptr, nullptr, nullptr, nullptr};
    const float* bs[4] = {nullptr, nullptr, nullptr, nullptr};
    int wi = 0, bi = 0;
    for (int i = 0; i < n_in; i++) {
        const long sz = in_sizes[i];
        if (sz == (long)Mtot * Dm)      x = (const float*)d_in[i];
        else if (sz == (long)Mtot)      am = (const int*)d_in[i];
        else if (sz == (long)Dm * Dm) { if (wi < 4) Ws[wi++] = (const float*)d_in[i]; }
        else if (sz == (long)Dm)      { if (bi < 4) bs[bi++] = (const float*)d_in[i]; }
    }

    __half *xf, *wf, *cf, *qf, *kf, *vf;
    cudaGetSymbolAddress((void**)&xf, g_xf);
    cudaGetSymbolAddress((void**)&wf, g_wf);
    cudaGetSymbolAddress((void**)&cf, g_cf);
    cudaGetSymbolAddress((void**)&qf, g_qf);
    cudaGetSymbolAddress((void**)&kf, g_kf);
    cudaGetSymbolAddress((void**)&vf, g_vf);

    cudaFuncSetAttribute(hmma_gemm_kernel<true>,
                         cudaFuncAttributeMaxDynamicSharedMemorySize, GEMM_SMEM);
    cudaFuncSetAttribute(hmma_gemm_kernel<false>,
                         cudaFuncAttributeMaxDynamicSharedMemorySize, GEMM_SMEM);
    cudaFuncSetAttribute(fa_hmma_kernel,
                         cudaFuncAttributeMaxDynamicSharedMemorySize, FA_SMEM);

    // Conversions
    const int n4x = Mtot * Dm / 4;
    const int n4w = Dm * Dm / 4;
    cvt_x_kernel<<<(n4x + 255) / 256, 256>>>(x, xf, n4x);
    cvt_w_kernel<<<dim3((n4w + 255) / 256, 4), 256>>>(
        Ws[0], Ws[1], Ws[2], Ws[3], wf);

    const size_t WSZ = (size_t)Dm * Dm;

    // Fused Q/K/V projections (all single-pass fp16); Q carries 0.125*log2e.
    const float QSCALE = 0.125f * 1.4426950408889634f;
    const dim3 gqkv(Dm / 128, Mtot / 128, 3);
    hmma_gemm_kernel<true><<<gqkv, 256, GEMM_SMEM>>>(
        xf,
        wf + 0 * WSZ, wf + 1 * WSZ, wf + 2 * WSZ,
        bs[0], bs[1], bs[2],
        nullptr,
        qf, kf, vf,
        QSCALE);

    // Attention (single-pass QK^T and PV, base-2 softmax)
    const dim3 ga(Sq / 64, Hh, Bc);
    fa_hmma_kernel<<<ga, 128, FA_SMEM>>>(qf, kf, vf, am, cf);

    // Output projection (single-pass fp16)
    const dim3 gg(Dm / 128, Mtot / 128, 1);
    hmma_gemm_kernel<false><<<gg, 256, GEMM_SMEM>>>(
        cf,
        wf + 3 * WSZ, wf + 3 * WSZ, wf + 3 * WSZ,
        bs[3], bs[3], bs[3],
        (float*)d_out,
        nullptr, nullptr, nullptr,
        1.0f);
}